// round 8
// baseline (speedup 1.0000x reference)
#include <cuda_runtime.h>
#include <cuda_fp16.h>
#include <math.h>
#include <stdint.h>

#define NMAX 100000
#define EMAX 1000000
#define GMAXG 512

// ---------------- scratch (device globals; no allocation allowed) ----------------
__device__ float   g_h[NMAX * 64];        // residual stream
__device__ float   g_t[NMAX * 64];        // post-attention / pre-BN buffer
__device__ __half2 g_qh[NMAX * 32];       // q fp16
__device__ __half2 g_kh[NMAX * 32];       // k fp16
__device__ __half2 g_vh[NMAX * 32];       // v fp16
__device__ __half2 g_ph[NMAX * 32];       // p_h = We_h @ q_h fp16
__device__ float   g_r[NMAX * 4];         // r_h = q_h . be_h
__device__ float   g_skip[NMAX * 64];
__device__ float   g_bnsum[64];
__device__ float   g_bnsq[64];
__device__ float   g_pool[GMAXG * 64];
__device__ float   g_cnt[GMAXG];
// CSR (built once per launch; edge list is layer-invariant)
__device__ int     g_cnt_n[NMAX];
__device__ int     g_row[NMAX + 1];
__device__ int     g_wp[NMAX];
__device__ int     g_bsum[128];
__device__ int     g_ssrc[EMAX];          // src sorted by dst
__device__ __half2 g_seah[EMAX * 8];      // edge_attr fp16, sorted by dst

static inline unsigned divup(long long a, int b) { return (unsigned)((a + b - 1) / b); }

__device__ __forceinline__ void redAddV4(float* addr, float a, float b, float c, float d) {
    asm volatile("red.global.add.v4.f32 [%0], {%1,%2,%3,%4};"
                 :: "l"(addr), "f"(a), "f"(b), "f"(c), "f"(d) : "memory");
}
__device__ __forceinline__ float2 h2f(unsigned u) {
    return __half22float2(*reinterpret_cast<const __half2*>(&u));
}

// ---------------- initial node linear: out[n,64] = in[n,32] @ W[32,64] + b ----------------
__global__ void lin32_kernel(const float* __restrict__ in, const float* __restrict__ W,
                             const float* __restrict__ bias, float* __restrict__ out, int n) {
    __shared__ float sW[32 * 64];
    __shared__ float sb[64];
    for (int i = threadIdx.x; i < 32 * 64; i += blockDim.x) sW[i] = W[i];
    if (threadIdx.x < 64) sb[threadIdx.x] = bias[threadIdx.x];
    __syncthreads();
    int node = blockIdx.x * blockDim.x + threadIdx.x;
    if (node >= n) return;
    float4 acc[16];
#pragma unroll
    for (int j = 0; j < 16; j++) {
        acc[j].x = sb[4 * j + 0]; acc[j].y = sb[4 * j + 1];
        acc[j].z = sb[4 * j + 2]; acc[j].w = sb[4 * j + 3];
    }
    const float4* inp = reinterpret_cast<const float4*>(in + (size_t)node * 32);
#pragma unroll
    for (int c = 0; c < 8; c++) {
        float4 x4 = inp[c];
        float xs[4] = {x4.x, x4.y, x4.z, x4.w};
#pragma unroll
        for (int kk = 0; kk < 4; kk++) {
            float x = xs[kk];
            const float4* wr = reinterpret_cast<const float4*>(&sW[(c * 4 + kk) * 64]);
#pragma unroll
            for (int j = 0; j < 16; j++) {
                float4 w = wr[j];
                acc[j].x += x * w.x; acc[j].y += x * w.y;
                acc[j].z += x * w.z; acc[j].w += x * w.w;
            }
        }
    }
    float4* op = reinterpret_cast<float4*>(out + (size_t)node * 64);
#pragma unroll
    for (int j = 0; j < 16; j++) op[j] = acc[j];
}

// ---------------- CSR build (once per launch) ----------------
__global__ void hist_clear_kernel(int n) {
    int i = blockIdx.x * blockDim.x + threadIdx.x;
    if (i < n) g_cnt_n[i] = 0;
}
__global__ void hist_kernel(const int* __restrict__ ei, int e) {
    int i = blockIdx.x * blockDim.x + threadIdx.x;
    if (i < e) atomicAdd(&g_cnt_n[ei[e + i]], 1);
}
__global__ void scan1_kernel(int n) {
    __shared__ int sm[1024];
    int i = blockIdx.x * 1024 + threadIdx.x;
    int v = (i < n) ? g_cnt_n[i] : 0;
    sm[threadIdx.x] = v;
    __syncthreads();
    for (int off = 1; off < 1024; off <<= 1) {
        int t = (threadIdx.x >= off) ? sm[threadIdx.x - off] : 0;
        __syncthreads();
        sm[threadIdx.x] += t;
        __syncthreads();
    }
    if (i < n) g_row[i + 1] = sm[threadIdx.x];
    if (threadIdx.x == 1023) g_bsum[blockIdx.x] = sm[1023];
}
__global__ void scan2_kernel(int nb) {
    if (threadIdx.x == 0) {
        int acc = 0;
        for (int b = 0; b < nb; b++) { int t = g_bsum[b]; g_bsum[b] = acc; acc += t; }
    }
}
__global__ void scan3_kernel(int n) {
    int i = blockIdx.x * 1024 + threadIdx.x;
    if (i < n) {
        int incl = g_row[i + 1] + g_bsum[blockIdx.x];
        g_row[i + 1] = incl;
        g_wp[i] = incl - g_cnt_n[i];
    }
    if (i == 0) g_row[0] = 0;
}
__global__ void scatter_kernel(const int* __restrict__ ei, const float* __restrict__ eattr, int e) {
    int eid = blockIdx.x * 256 + threadIdx.x;
    if (eid >= e) return;
    int dst = ei[e + eid];
    int pos = atomicAdd(&g_wp[dst], 1);
    g_ssrc[pos] = ei[eid];
    const float4* ea = reinterpret_cast<const float4*>(eattr + (size_t)eid * 16);
    __half2 hp[8];
#pragma unroll
    for (int jj = 0; jj < 4; jj++) {
        float4 v = ea[jj];
        hp[2 * jj]     = __floats2half2_rn(v.x, v.y);
        hp[2 * jj + 1] = __floats2half2_rn(v.z, v.w);
    }
    uint4* dp = reinterpret_cast<uint4*>(g_seah + (size_t)pos * 8);
    dp[0] = *reinterpret_cast<uint4*>(&hp[0]);
    dp[1] = *reinterpret_cast<uint4*>(&hp[4]);
}

// ---------------- fused q/k/v/skip + p/r precompute (q/k/v/p stored fp16) ----------------
__global__ void qkvs_kernel(const float* __restrict__ h,
                            const float* __restrict__ Wq, const float* __restrict__ bq,
                            const float* __restrict__ Wk, const float* __restrict__ bk,
                            const float* __restrict__ Wv, const float* __restrict__ bv,
                            const float* __restrict__ Ws, const float* __restrict__ bs,
                            const float* __restrict__ We, const float* __restrict__ be,
                            int n) {
    __shared__ float xs[64 * 65];
    __shared__ float sW[64 * 64];
    __shared__ float sb[64];
    __shared__ float sWe[16 * 64];
    __shared__ float sbe[64];
    const int tid = threadIdx.x;
    const int base = blockIdx.x * 64;

    if (blockIdx.x == 0 && tid < 64) { g_bnsum[tid] = 0.0f; g_bnsq[tid] = 0.0f; }

    for (int idx = tid; idx < 64 * 16; idx += 256) {
        int nl = idx >> 4, kk = idx & 15;
        int gn = base + nl;
        if (gn < n) {
            float4 x4 = reinterpret_cast<const float4*>(h + (size_t)gn * 64)[kk];
            float* p = &xs[nl * 65 + kk * 4];
            p[0] = x4.x; p[1] = x4.y; p[2] = x4.z; p[3] = x4.w;
        }
    }
    for (int i = tid; i < 1024; i += 256) sWe[i] = We[i];
    if (tid < 64) sbe[tid] = be[tid];

    const float* Wm[4] = {Wq, Wk, Wv, Ws};
    const float* bm[4] = {bq, bk, bv, bs};

    const int nl = tid & 63;
    const int quart = tid >> 6;            // head index
    const int gn = base + nl;

#pragma unroll
    for (int m = 0; m < 4; m++) {
        __syncthreads();
        {
            const float4* wsrc = reinterpret_cast<const float4*>(Wm[m]);
            float4* wdst = reinterpret_cast<float4*>(sW);
            for (int i = tid; i < 1024; i += 256) wdst[i] = wsrc[i];
            if (tid < 64) sb[tid] = bm[m][tid];
        }
        __syncthreads();
        if (gn < n) {
            float4 acc[4];
#pragma unroll
            for (int j = 0; j < 4; j++) {
                acc[j].x = sb[quart * 16 + 4 * j + 0];
                acc[j].y = sb[quart * 16 + 4 * j + 1];
                acc[j].z = sb[quart * 16 + 4 * j + 2];
                acc[j].w = sb[quart * 16 + 4 * j + 3];
            }
            const float* xrow = &xs[nl * 65];
#pragma unroll 8
            for (int k = 0; k < 64; k++) {
                float x = xrow[k];
                const float4* wr = reinterpret_cast<const float4*>(&sW[k * 64 + quart * 16]);
#pragma unroll
                for (int j = 0; j < 4; j++) {
                    float4 w = wr[j];
                    acc[j].x += x * w.x; acc[j].y += x * w.y;
                    acc[j].z += x * w.z; acc[j].w += x * w.w;
                }
            }

            if (m == 3) {
                float4* op = reinterpret_cast<float4*>(g_skip + (size_t)gn * 64 + quart * 16);
#pragma unroll
                for (int j = 0; j < 4; j++) op[j] = acc[j];
            } else {
                __half2* hb = (m == 0 ? g_qh : (m == 1 ? g_kh : g_vh));
                __half2 hp[8];
#pragma unroll
                for (int j = 0; j < 4; j++) {
                    hp[2 * j]     = __floats2half2_rn(acc[j].x, acc[j].y);
                    hp[2 * j + 1] = __floats2half2_rn(acc[j].z, acc[j].w);
                }
                uint4* dstp = reinterpret_cast<uint4*>(hb + (size_t)gn * 32 + quart * 8);
                dstp[0] = *reinterpret_cast<uint4*>(&hp[0]);
                dstp[1] = *reinterpret_cast<uint4*>(&hp[4]);
            }

            if (m == 0) {
                float qv[16];
#pragma unroll
                for (int j = 0; j < 4; j++) {
                    qv[4 * j + 0] = acc[j].x; qv[4 * j + 1] = acc[j].y;
                    qv[4 * j + 2] = acc[j].z; qv[4 * j + 3] = acc[j].w;
                }
                float pc[16];
#pragma unroll
                for (int c = 0; c < 16; c++) {
                    const float4* wr = reinterpret_cast<const float4*>(&sWe[c * 64 + quart * 16]);
                    float s = 0.0f;
#pragma unroll
                    for (int j = 0; j < 4; j++) {
                        float4 w = wr[j];
                        s += w.x * qv[4 * j] + w.y * qv[4 * j + 1]
                           + w.z * qv[4 * j + 2] + w.w * qv[4 * j + 3];
                    }
                    pc[c] = s;
                }
                float rr = 0.0f;
#pragma unroll
                for (int d = 0; d < 16; d++) rr += sbe[quart * 16 + d] * qv[d];
                __half2 hp[8];
#pragma unroll
                for (int j = 0; j < 8; j++) hp[j] = __floats2half2_rn(pc[2 * j], pc[2 * j + 1]);
                uint4* pp = reinterpret_cast<uint4*>(g_ph + (size_t)gn * 32 + quart * 8);
                pp[0] = *reinterpret_cast<uint4*>(&hp[0]);
                pp[1] = *reinterpret_cast<uint4*>(&hp[4]);
                g_r[gn * 4 + quart] = rr;
            }
        }
    }
}

// ---------------- fused edge aggregation + finalize + BN stats ----------------
// One warp per dst node (8 edge-slots x 4 lanes). No atomics on t; CSR-sorted edges.
__global__ void edge_agg_kernel(const float* __restrict__ We, const float* __restrict__ be, int n) {
    __shared__ float sWe[16 * 64];
    __shared__ float sbe[64];
    __shared__ float smsum[64];
    __shared__ float smsq[64];
    const int tid = threadIdx.x;
    for (int i = tid; i < 1024; i += 256) sWe[i] = We[i];
    if (tid < 64) { sbe[tid] = be[tid]; smsum[tid] = 0.0f; smsq[tid] = 0.0f; }
    __syncthreads();

    const int lane = tid & 31;
    const int j = lane & 3;          // dim-chunk within head
    const int slot = lane >> 2;      // edge slot 0..7
    const int node = blockIdx.x * 8 + (tid >> 5);
    const unsigned gmask = 0xFu << (lane & 28);

    if (node < n) {
        // dst-side operands, loaded once
        const uint2* qb = reinterpret_cast<const uint2*>(g_qh + (size_t)node * 32 + j * 2);
        const uint2* pb = reinterpret_cast<const uint2*>(g_ph + (size_t)node * 32 + j * 2);
        uint2 qv[4], pv[4];
#pragma unroll
        for (int i = 0; i < 4; i++) { qv[i] = qb[i * 4]; pv[i] = pb[i * 4]; }
        float4 rr = *reinterpret_cast<const float4*>(g_r + (size_t)node * 4);

        int rs = g_row[node], re = g_row[node + 1];
        float at[4][4], as[4][4], ad[4];
#pragma unroll
        for (int i = 0; i < 4; i++) {
            ad[i] = 0.0f;
#pragma unroll
            for (int d = 0; d < 4; d++) { at[i][d] = 0.0f; as[i][d] = 0.0f; }
        }

        for (int basee = rs; basee < re; basee += 8) {
            int eix = basee + slot;
            if (eix < re) {
                int src = g_ssrc[eix];
                uint2 eaw = *reinterpret_cast<const uint2*>(g_seah + (size_t)eix * 8 + j * 2);
                float2 ea0 = h2f(eaw.x), ea1 = h2f(eaw.y);
                const uint2* kb = reinterpret_cast<const uint2*>(g_kh + (size_t)src * 32 + j * 2);
                const uint2* vb = reinterpret_cast<const uint2*>(g_vh + (size_t)src * 32 + j * 2);

                float part[4];
#pragma unroll
                for (int i = 0; i < 4; i++) {
                    uint2 kr = kb[i * 4];
                    float2 q0 = h2f(qv[i].x), q1 = h2f(qv[i].y);
                    float2 k0 = h2f(kr.x),  k1 = h2f(kr.y);
                    float2 p0 = h2f(pv[i].x), p1 = h2f(pv[i].y);
                    part[i] = q0.x * k0.x + q0.y * k0.y + q1.x * k1.x + q1.y * k1.y
                            + p0.x * ea0.x + p0.y * ea0.y + p1.x * ea1.x + p1.y * ea1.y;
                }
#pragma unroll
                for (int off = 1; off < 4; off <<= 1) {
#pragma unroll
                    for (int i = 0; i < 4; i++) part[i] += __shfl_xor_sync(gmask, part[i], off);
                }
                float exv[4];
                exv[0] = __expf((part[0] + rr.x) * 0.25f);
                exv[1] = __expf((part[1] + rr.y) * 0.25f);
                exv[2] = __expf((part[2] + rr.z) * 0.25f);
                exv[3] = __expf((part[3] + rr.w) * 0.25f);
#pragma unroll
                for (int i = 0; i < 4; i++) {
                    ad[i] += exv[i];
                    uint2 vr = vb[i * 4];
                    float2 v0 = h2f(vr.x), v1 = h2f(vr.y);
                    at[i][0] += exv[i] * v0.x; at[i][1] += exv[i] * v0.y;
                    at[i][2] += exv[i] * v1.x; at[i][3] += exv[i] * v1.y;
                    as[i][0] += exv[i] * ea0.x; as[i][1] += exv[i] * ea0.y;
                    as[i][2] += exv[i] * ea1.x; as[i][3] += exv[i] * ea1.y;
                }
            }
        }

        // butterfly across the 8 slots (lanes with same j)
#pragma unroll
        for (int off = 4; off < 32; off <<= 1) {
#pragma unroll
            for (int i = 0; i < 4; i++) {
                ad[i] += __shfl_xor_sync(0xffffffffu, ad[i], off);
#pragma unroll
                for (int d = 0; d < 4; d++) {
                    at[i][d] += __shfl_xor_sync(0xffffffffu, at[i][d], off);
                    as[i][d] += __shfl_xor_sync(0xffffffffu, as[i][d], off);
                }
            }
        }

        // epilogue: w = We_h^T s_h ; t = (t + w + den*be)/(den+eps) + skip
#pragma unroll
        for (int i = 0; i < 4; i++) {
            float w0 = 0.f, w1 = 0.f, w2 = 0.f, w3 = 0.f;
#pragma unroll
            for (int srcl = 0; srcl < 4; srcl++) {
#pragma unroll
                for (int cc = 0; cc < 4; cc++) {
                    float sc = __shfl_sync(0xffffffffu, as[i][cc], srcl, 4);
                    float4 ww = *reinterpret_cast<const float4*>(
                        &sWe[(srcl * 4 + cc) * 64 + i * 16 + j * 4]);
                    w0 += sc * ww.x; w1 += sc * ww.y; w2 += sc * ww.z; w3 += sc * ww.w;
                }
            }
            float den = ad[i];
            float inv = 1.0f / (den + 1e-16f);
            float4 sk = *reinterpret_cast<const float4*>(g_skip + (size_t)node * 64 + i * 16 + j * 4);
            int ch = i * 16 + j * 4;
            float o0 = (at[i][0] + w0 + den * sbe[ch + 0]) * inv + sk.x;
            float o1 = (at[i][1] + w1 + den * sbe[ch + 1]) * inv + sk.y;
            float o2 = (at[i][2] + w2 + den * sbe[ch + 2]) * inv + sk.z;
            float o3 = (at[i][3] + w3 + den * sbe[ch + 3]) * inv + sk.w;
            if (slot == 0) {
                float4 o; o.x = o0; o.y = o1; o.z = o2; o.w = o3;
                *reinterpret_cast<float4*>(g_t + (size_t)node * 64 + ch) = o;
                atomicAdd(&smsum[ch + 0], o0); atomicAdd(&smsq[ch + 0], o0 * o0);
                atomicAdd(&smsum[ch + 1], o1); atomicAdd(&smsq[ch + 1], o1 * o1);
                atomicAdd(&smsum[ch + 2], o2); atomicAdd(&smsq[ch + 2], o2 * o2);
                atomicAdd(&smsum[ch + 3], o3); atomicAdd(&smsq[ch + 3], o3 * o3);
            }
        }
    }
    __syncthreads();
    if (tid < 64) {
        atomicAdd(&g_bnsum[tid], smsum[tid]);
        atomicAdd(&g_bnsq[tid], smsq[tid]);
    }
}

// ---------------- BN apply + GELU + residual ----------------
__global__ void bn_apply_kernel(const float* __restrict__ gamma, const float* __restrict__ beta, int n) {
    int idx = blockIdx.x * blockDim.x + threadIdx.x;
    if (idx >= n * 16) return;
    int c0 = (idx & 15) * 4;
    float invN = 1.0f / (float)n;
    float4 tv = reinterpret_cast<const float4*>(g_t)[idx];
    float4 hv = reinterpret_cast<const float4*>(g_h)[idx];
    float tt[4] = {tv.x, tv.y, tv.z, tv.w};
    float hh[4] = {hv.x, hv.y, hv.z, hv.w};
    float r[4];
#pragma unroll
    for (int k = 0; k < 4; k++) {
        int c = c0 + k;
        float mu = g_bnsum[c] * invN;
        float var = g_bnsq[c] * invN - mu * mu;
        float y = gamma[c] * (tt[k] - mu) * rsqrtf(var + 1e-5f) + beta[c];
        float gl = 0.5f * y * (1.0f + erff(y * 0.70710678118654752f));
        r[k] = gl + hh[k];
    }
    float4 o; o.x = r[0]; o.y = r[1]; o.z = r[2]; o.w = r[3];
    reinterpret_cast<float4*>(g_h)[idx] = o;
}

// ---------------- pooling ----------------
__global__ void clear_pool_kernel(int G) {
    int i = blockIdx.x * blockDim.x + threadIdx.x;
    if (i < G * 64) g_pool[i] = 0.0f;
    if (i < G) g_cnt[i] = 0.0f;
}

__global__ void pool_kernel(const int* __restrict__ batch, int n) {
    int idx = blockIdx.x * blockDim.x + threadIdx.x;
    if (idx >= n * 16) return;
    int node = idx >> 4, c4 = idx & 15;
    int g = batch[node];
    float4 v = reinterpret_cast<const float4*>(g_h)[idx];
    redAddV4(&g_pool[g * 64 + c4 * 4], v.x, v.y, v.z, v.w);
    if (c4 == 0) atomicAdd(&g_cnt[g], 1.0f);
}

// ---------------- regressor ----------------
__global__ void reg_kernel(const float* __restrict__ rw1, const float* __restrict__ rb1,
                           const float* __restrict__ rw2, const float* __restrict__ rb2,
                           float* __restrict__ out) {
    int g = blockIdx.x;
    int tid = threadIdx.x;  // 128 threads
    __shared__ float feat[128];
    __shared__ float hred[64];
    float invc = 1.0f / fmaxf(g_cnt[g], 1.0f);
    float s = g_pool[g * 64 + (tid & 63)];
    feat[tid] = (tid < 64) ? s * invc : s;
    __syncthreads();
    if (tid < 64) {
        float acc = rb1[tid];
#pragma unroll 8
        for (int i = 0; i < 128; i++) acc += feat[i] * rw1[i * 64 + tid];
        acc = fmaxf(acc, 0.0f);
        hred[tid] = acc * rw2[tid];
    }
    __syncthreads();
    if (tid < 32) {
        float v = hred[tid] + hred[tid + 32];
#pragma unroll
        for (int off = 16; off > 0; off >>= 1) v += __shfl_down_sync(0xffffffffu, v, off);
        if (tid == 0) out[g] = v + rb2[0];
    }
}

// ---------------- host orchestration ----------------
extern "C" void kernel_launch(void* const* d_in, const int* in_sizes, int n_in,
                              void* d_out, int out_size) {
    const float* x      = (const float*)d_in[0];
    const int*   ei     = (const int*)d_in[1];
    const float* eattr  = (const float*)d_in[2];
    const int*   batch  = (const int*)d_in[3];
    const float* node_w = (const float*)d_in[4];
    const float* node_b = (const float*)d_in[5];
    const float* Wq = (const float*)d_in[6];
    const float* bq = (const float*)d_in[7];
    const float* Wk = (const float*)d_in[8];
    const float* bk = (const float*)d_in[9];
    const float* Wv = (const float*)d_in[10];
    const float* bv = (const float*)d_in[11];
    const float* We = (const float*)d_in[12];
    const float* be = (const float*)d_in[13];
    const float* Ws = (const float*)d_in[14];
    const float* bs = (const float*)d_in[15];
    const float* gamma = (const float*)d_in[16];
    const float* beta  = (const float*)d_in[17];
    const float* rw1 = (const float*)d_in[18];
    const float* rb1 = (const float*)d_in[19];
    const float* rw2 = (const float*)d_in[20];
    const float* rb2 = (const float*)d_in[21];
    float* out = (float*)d_out;

    int n = in_sizes[0] / 32;   // nodes
    int e = in_sizes[2] / 16;   // edges
    int G = out_size;           // graphs
    int nb = divup(n, 1024);

    float* ph;
    cudaGetSymbolAddress((void**)&ph, g_h);

    lin32_kernel<<<divup(n, 128), 128>>>(x, node_w, node_b, ph, n);

    // Build dst-CSR + sorted fp16 edge_attr (once; reused by all 3 layers)
    hist_clear_kernel<<<divup(n, 256), 256>>>(n);
    hist_kernel<<<divup(e, 256), 256>>>(ei, e);
    scan1_kernel<<<nb, 1024>>>(n);
    scan2_kernel<<<1, 32>>>(nb);
    scan3_kernel<<<nb, 1024>>>(n);
    scatter_kernel<<<divup(e, 256), 256>>>(ei, eattr, e);

    for (int l = 0; l < 3; l++) {
        const float* wq = Wq + (size_t)l * 64 * 64;
        const float* wk = Wk + (size_t)l * 64 * 64;
        const float* wv = Wv + (size_t)l * 64 * 64;
        const float* ws = Ws + (size_t)l * 64 * 64;
        const float* we = We + (size_t)l * 16 * 64;

        qkvs_kernel<<<divup(n, 64), 256>>>(ph, wq, bq + l * 64, wk, bk + l * 64,
                                           wv, bv + l * 64, ws, bs + l * 64,
                                           we, be + l * 64, n);
        edge_agg_kernel<<<divup(n, 8), 256>>>(we, be + l * 64, n);
        bn_apply_kernel<<<divup((long long)n * 16, 256), 256>>>(gamma + l * 64, beta + l * 64, n);
    }

    clear_pool_kernel<<<divup((long long)G * 64, 256), 256>>>(G);
    pool_kernel<<<divup((long long)n * 16, 256), 256>>>(batch, n);
    reg_kernel<<<G, 128>>>(rw1, rb1, rw2, rb2, out);
}

// round 9
// speedup vs baseline: 1.4111x; 1.4111x over previous
#include <cuda_runtime.h>
#include <cuda_fp16.h>
#include <math.h>
#include <stdint.h>

#define NMAX 100000
#define EMAX 1000000
#define GMAXG 512

// ---------------- scratch (device globals; no allocation allowed) ----------------
__device__ float   g_h[NMAX * 64];        // residual stream
__device__ float   g_t[NMAX * 64];        // attn accumulator (ex*v sums) / pre-BN buffer
__device__ float   g_s[NMAX * 64];        // per (node,head) sum of ex*edge_attr
__device__ __half2 g_qh[NMAX * 32];       // q fp16
__device__ __half2 g_kh[NMAX * 32];       // k fp16
__device__ __half2 g_vh[NMAX * 32];       // v fp16
__device__ __half2 g_ph[NMAX * 32];       // p_h = We_h @ q_h fp16
__device__ float   g_r[NMAX * 4];         // r_h = q_h . be_h
__device__ float   g_skip[NMAX * 64];
__device__ float   g_denom[NMAX * 4];
__device__ float   g_bnsum[64];
__device__ float   g_bnsq[64];
__device__ float   g_pool[GMAXG * 64];
__device__ float   g_cnt[GMAXG];
// CSR / sorted edge stream (built once per launch; edge list is layer-invariant)
__device__ int     g_cnt_n[NMAX];
__device__ int     g_row[NMAX + 1];
__device__ int     g_wp[NMAX];
__device__ int     g_bsum[128];
__device__ int     g_ssrc[EMAX];          // src sorted by dst
__device__ int     g_sdst[EMAX];          // dst sorted (non-decreasing)
__device__ __half2 g_seah[EMAX * 8];      // edge_attr fp16, sorted by dst

static inline unsigned divup(long long a, int b) { return (unsigned)((a + b - 1) / b); }

__device__ __forceinline__ void redAddV4(float* addr, float a, float b, float c, float d) {
    asm volatile("red.global.add.v4.f32 [%0], {%1,%2,%3,%4};"
                 :: "l"(addr), "f"(a), "f"(b), "f"(c), "f"(d) : "memory");
}
__device__ __forceinline__ float2 h2f(unsigned u) {
    return __half22float2(*reinterpret_cast<const __half2*>(&u));
}

// ---------------- initial node linear: out[n,64] = in[n,32] @ W[32,64] + b ----------------
__global__ void lin32_kernel(const float* __restrict__ in, const float* __restrict__ W,
                             const float* __restrict__ bias, float* __restrict__ out, int n) {
    __shared__ float sW[32 * 64];
    __shared__ float sb[64];
    for (int i = threadIdx.x; i < 32 * 64; i += blockDim.x) sW[i] = W[i];
    if (threadIdx.x < 64) sb[threadIdx.x] = bias[threadIdx.x];
    __syncthreads();
    int node = blockIdx.x * blockDim.x + threadIdx.x;
    if (node >= n) return;
    float4 acc[16];
#pragma unroll
    for (int j = 0; j < 16; j++) {
        acc[j].x = sb[4 * j + 0]; acc[j].y = sb[4 * j + 1];
        acc[j].z = sb[4 * j + 2]; acc[j].w = sb[4 * j + 3];
    }
    const float4* inp = reinterpret_cast<const float4*>(in + (size_t)node * 32);
#pragma unroll
    for (int c = 0; c < 8; c++) {
        float4 x4 = inp[c];
        float xs[4] = {x4.x, x4.y, x4.z, x4.w};
#pragma unroll
        for (int kk = 0; kk < 4; kk++) {
            float x = xs[kk];
            const float4* wr = reinterpret_cast<const float4*>(&sW[(c * 4 + kk) * 64]);
#pragma unroll
            for (int j = 0; j < 16; j++) {
                float4 w = wr[j];
                acc[j].x += x * w.x; acc[j].y += x * w.y;
                acc[j].z += x * w.z; acc[j].w += x * w.w;
            }
        }
    }
    float4* op = reinterpret_cast<float4*>(out + (size_t)node * 64);
#pragma unroll
    for (int j = 0; j < 16; j++) op[j] = acc[j];
}

// ---------------- CSR build (once per launch) ----------------
__global__ void hist_clear_kernel(int n) {
    int i = blockIdx.x * blockDim.x + threadIdx.x;
    if (i < n) g_cnt_n[i] = 0;
}
__global__ void hist_kernel(const int* __restrict__ ei, int e) {
    int i = blockIdx.x * blockDim.x + threadIdx.x;
    if (i < e) atomicAdd(&g_cnt_n[ei[e + i]], 1);
}
__global__ void scan1_kernel(int n) {
    __shared__ int sm[1024];
    int i = blockIdx.x * 1024 + threadIdx.x;
    int v = (i < n) ? g_cnt_n[i] : 0;
    sm[threadIdx.x] = v;
    __syncthreads();
    for (int off = 1; off < 1024; off <<= 1) {
        int t = (threadIdx.x >= off) ? sm[threadIdx.x - off] : 0;
        __syncthreads();
        sm[threadIdx.x] += t;
        __syncthreads();
    }
    if (i < n) g_row[i + 1] = sm[threadIdx.x];
    if (threadIdx.x == 1023) g_bsum[blockIdx.x] = sm[1023];
}
__global__ void scan2_kernel(int nb) {
    if (threadIdx.x == 0) {
        int acc = 0;
        for (int b = 0; b < nb; b++) { int t = g_bsum[b]; g_bsum[b] = acc; acc += t; }
    }
}
__global__ void scan3_kernel(int n) {
    int i = blockIdx.x * 1024 + threadIdx.x;
    if (i < n) {
        int incl = g_row[i + 1] + g_bsum[blockIdx.x];
        g_row[i + 1] = incl;
        g_wp[i] = incl - g_cnt_n[i];
    }
    if (i == 0) g_row[0] = 0;
}
__global__ void scatter_kernel(const int* __restrict__ ei, const float* __restrict__ eattr, int e) {
    int eid = blockIdx.x * 256 + threadIdx.x;
    if (eid >= e) return;
    int dst = ei[e + eid];
    int pos = atomicAdd(&g_wp[dst], 1);
    g_ssrc[pos] = ei[eid];
    g_sdst[pos] = dst;
    const float4* ea = reinterpret_cast<const float4*>(eattr + (size_t)eid * 16);
    __half2 hp[8];
#pragma unroll
    for (int jj = 0; jj < 4; jj++) {
        float4 v = ea[jj];
        hp[2 * jj]     = __floats2half2_rn(v.x, v.y);
        hp[2 * jj + 1] = __floats2half2_rn(v.z, v.w);
    }
    uint4* dp = reinterpret_cast<uint4*>(g_seah + (size_t)pos * 8);
    dp[0] = *reinterpret_cast<uint4*>(&hp[0]);
    dp[1] = *reinterpret_cast<uint4*>(&hp[4]);
}

// ---------------- fused q/k/v/skip + p/r precompute + t/s/denom clear ----------------
// block = 256 threads = 64 nodes x 4 column-quarters (quart == head)
__global__ void qkvs_kernel(const float* __restrict__ h,
                            const float* __restrict__ Wq, const float* __restrict__ bq,
                            const float* __restrict__ Wk, const float* __restrict__ bk,
                            const float* __restrict__ Wv, const float* __restrict__ bv,
                            const float* __restrict__ Ws, const float* __restrict__ bs,
                            const float* __restrict__ We, const float* __restrict__ be,
                            int n) {
    __shared__ float xs[64 * 65];
    __shared__ float sW[64 * 64];
    __shared__ float sb[64];
    __shared__ float sWe[16 * 64];
    __shared__ float sbe[64];
    const int tid = threadIdx.x;
    const int base = blockIdx.x * 64;

    if (blockIdx.x == 0 && tid < 64) { g_bnsum[tid] = 0.0f; g_bnsq[tid] = 0.0f; }

    // clear this block's slice of t/s/denom (replaces the standalone clear kernel)
    {
        float4 z; z.x = 0.f; z.y = 0.f; z.z = 0.f; z.w = 0.f;
        int lim = n * 16;
        for (int i = tid; i < 1024; i += 256) {
            int gi = base * 16 + i;
            if (gi < lim) {
                reinterpret_cast<float4*>(g_t)[gi] = z;
                reinterpret_cast<float4*>(g_s)[gi] = z;
            }
        }
        if (tid < 64 && base + tid < n) reinterpret_cast<float4*>(g_denom)[base + tid] = z;
    }

    for (int idx = tid; idx < 64 * 16; idx += 256) {
        int nl = idx >> 4, kk = idx & 15;
        int gn = base + nl;
        if (gn < n) {
            float4 x4 = reinterpret_cast<const float4*>(h + (size_t)gn * 64)[kk];
            float* p = &xs[nl * 65 + kk * 4];
            p[0] = x4.x; p[1] = x4.y; p[2] = x4.z; p[3] = x4.w;
        }
    }
    for (int i = tid; i < 1024; i += 256) sWe[i] = We[i];
    if (tid < 64) sbe[tid] = be[tid];

    const float* Wm[4] = {Wq, Wk, Wv, Ws};
    const float* bm[4] = {bq, bk, bv, bs};

    const int nl = tid & 63;
    const int quart = tid >> 6;            // head index
    const int gn = base + nl;

#pragma unroll
    for (int m = 0; m < 4; m++) {
        __syncthreads();
        {
            const float4* wsrc = reinterpret_cast<const float4*>(Wm[m]);
            float4* wdst = reinterpret_cast<float4*>(sW);
            for (int i = tid; i < 1024; i += 256) wdst[i] = wsrc[i];
            if (tid < 64) sb[tid] = bm[m][tid];
        }
        __syncthreads();
        if (gn < n) {
            float4 acc[4];
#pragma unroll
            for (int j = 0; j < 4; j++) {
                acc[j].x = sb[quart * 16 + 4 * j + 0];
                acc[j].y = sb[quart * 16 + 4 * j + 1];
                acc[j].z = sb[quart * 16 + 4 * j + 2];
                acc[j].w = sb[quart * 16 + 4 * j + 3];
            }
            const float* xrow = &xs[nl * 65];
#pragma unroll 8
            for (int k = 0; k < 64; k++) {
                float x = xrow[k];
                const float4* wr = reinterpret_cast<const float4*>(&sW[k * 64 + quart * 16]);
#pragma unroll
                for (int j = 0; j < 4; j++) {
                    float4 w = wr[j];
                    acc[j].x += x * w.x; acc[j].y += x * w.y;
                    acc[j].z += x * w.z; acc[j].w += x * w.w;
                }
            }

            if (m == 3) {
                float4* op = reinterpret_cast<float4*>(g_skip + (size_t)gn * 64 + quart * 16);
#pragma unroll
                for (int j = 0; j < 4; j++) op[j] = acc[j];
            } else {
                __half2* hb = (m == 0 ? g_qh : (m == 1 ? g_kh : g_vh));
                __half2 hp[8];
#pragma unroll
                for (int j = 0; j < 4; j++) {
                    hp[2 * j]     = __floats2half2_rn(acc[j].x, acc[j].y);
                    hp[2 * j + 1] = __floats2half2_rn(acc[j].z, acc[j].w);
                }
                uint4* dstp = reinterpret_cast<uint4*>(hb + (size_t)gn * 32 + quart * 8);
                dstp[0] = *reinterpret_cast<uint4*>(&hp[0]);
                dstp[1] = *reinterpret_cast<uint4*>(&hp[4]);
            }

            if (m == 0) {
                float qv[16];
#pragma unroll
                for (int j = 0; j < 4; j++) {
                    qv[4 * j + 0] = acc[j].x; qv[4 * j + 1] = acc[j].y;
                    qv[4 * j + 2] = acc[j].z; qv[4 * j + 3] = acc[j].w;
                }
                float pc[16];
#pragma unroll
                for (int c = 0; c < 16; c++) {
                    const float4* wr = reinterpret_cast<const float4*>(&sWe[c * 64 + quart * 16]);
                    float s = 0.0f;
#pragma unroll
                    for (int j = 0; j < 4; j++) {
                        float4 w = wr[j];
                        s += w.x * qv[4 * j] + w.y * qv[4 * j + 1]
                           + w.z * qv[4 * j + 2] + w.w * qv[4 * j + 3];
                    }
                    pc[c] = s;
                }
                float rr = 0.0f;
#pragma unroll
                for (int d = 0; d < 16; d++) rr += sbe[quart * 16 + d] * qv[d];
                __half2 hp[8];
#pragma unroll
                for (int j = 0; j < 8; j++) hp[j] = __floats2half2_rn(pc[2 * j], pc[2 * j + 1]);
                uint4* pp = reinterpret_cast<uint4*>(g_ph + (size_t)gn * 32 + quart * 8);
                pp[0] = *reinterpret_cast<uint4*>(&hp[0]);
                pp[1] = *reinterpret_cast<uint4*>(&hp[4]);
                g_r[gn * 4 + quart] = rr;
            }
        }
    }
}

// ---------------- single fused edge pass over the dst-sorted edge stream ----------------
// 4 lanes per edge; lane j owns dims [j*4, j*4+4) of every head.
__global__ void edge_fused_kernel(int e) {
    int idx = blockIdx.x * 256 + threadIdx.x;
    if (idx >= e * 4) return;
    int eix = idx >> 2, j = idx & 3;
    int src = g_ssrc[eix];
    int dst = g_sdst[eix];

    uint2 eaw = *reinterpret_cast<const uint2*>(g_seah + (size_t)eix * 8 + j * 2);
    float2 ea0 = h2f(eaw.x), ea1 = h2f(eaw.y);

    const uint2* qb = reinterpret_cast<const uint2*>(g_qh + (size_t)dst * 32 + j * 2);
    const uint2* kb = reinterpret_cast<const uint2*>(g_kh + (size_t)src * 32 + j * 2);
    const uint2* pb = reinterpret_cast<const uint2*>(g_ph + (size_t)dst * 32 + j * 2);

    float part[4];
#pragma unroll
    for (int i = 0; i < 4; i++) {
        uint2 qr = qb[i * 4];
        uint2 kr = kb[i * 4];
        uint2 pr = pb[i * 4];
        float2 q0 = h2f(qr.x), q1 = h2f(qr.y);
        float2 k0 = h2f(kr.x), k1 = h2f(kr.y);
        float2 p0 = h2f(pr.x), p1 = h2f(pr.y);
        part[i] = q0.x * k0.x + q0.y * k0.y + q1.x * k1.x + q1.y * k1.y
                + p0.x * ea0.x + p0.y * ea0.y + p1.x * ea1.x + p1.y * ea1.y;
    }
    part[j] += g_r[dst * 4 + j];   // after cross-lane sum, head h receives r_h exactly once

    unsigned lane = threadIdx.x & 31;
    unsigned gmask = 0xFu << (lane & 28);
#pragma unroll
    for (int off = 1; off < 4; off <<= 1) {
#pragma unroll
        for (int i = 0; i < 4; i++) part[i] += __shfl_xor_sync(gmask, part[i], off);
    }

    float ex[4];
#pragma unroll
    for (int i = 0; i < 4; i++) ex[i] = __expf(part[i] * 0.25f);

    if (j == 0) redAddV4(&g_denom[dst * 4], ex[0], ex[1], ex[2], ex[3]);

    const uint2* vb = reinterpret_cast<const uint2*>(g_vh + (size_t)src * 32 + j * 2);
    float* tb = g_t + (size_t)dst * 64 + j * 4;
    float* sb = g_s + (size_t)dst * 64 + j * 4;
#pragma unroll
    for (int i = 0; i < 4; i++) {
        uint2 vr = vb[i * 4];
        float2 v0 = h2f(vr.x), v1 = h2f(vr.y);
        redAddV4(tb + i * 16, ex[i] * v0.x, ex[i] * v0.y, ex[i] * v1.x, ex[i] * v1.y);
        redAddV4(sb + i * 16, ex[i] * ea0.x, ex[i] * ea0.y, ex[i] * ea1.x, ex[i] * ea1.y);
    }
}

// ---------------- finalize: t = (t + We_h^T s + denom*be_h)/(denom+1e-16) + skip ----------------
__global__ void finalize_attn_kernel(const float* __restrict__ We, const float* __restrict__ be, int n) {
    __shared__ float sWe[16 * 64];
    __shared__ float sbe[64];
    const int tid = threadIdx.x;
    for (int i = tid; i < 1024; i += 256) sWe[i] = We[i];
    if (tid < 64) sbe[tid] = be[tid];
    __syncthreads();

    int idx = blockIdx.x * 256 + tid;  // (node, head)
    if (idx >= n * 4) return;
    int node = idx >> 2, h = idx & 3;
    float den = g_denom[idx];
    float inv = 1.0f / (den + 1e-16f);

    const float4* sv = reinterpret_cast<const float4*>(g_s + (size_t)node * 64 + h * 16);
    float sarr[16];
#pragma unroll
    for (int j = 0; j < 4; j++) {
        float4 s4 = sv[j];
        sarr[4 * j] = s4.x; sarr[4 * j + 1] = s4.y; sarr[4 * j + 2] = s4.z; sarr[4 * j + 3] = s4.w;
    }
    float4 w[4];
#pragma unroll
    for (int j = 0; j < 4; j++) { w[j].x = 0.f; w[j].y = 0.f; w[j].z = 0.f; w[j].w = 0.f; }
#pragma unroll
    for (int c = 0; c < 16; c++) {
        float sc = sarr[c];
        const float4* wr = reinterpret_cast<const float4*>(&sWe[c * 64 + h * 16]);
#pragma unroll
        for (int j = 0; j < 4; j++) {
            float4 ww = wr[j];
            w[j].x += sc * ww.x; w[j].y += sc * ww.y;
            w[j].z += sc * ww.z; w[j].w += sc * ww.w;
        }
    }
    float4* tp = reinterpret_cast<float4*>(g_t + (size_t)node * 64 + h * 16);
    const float4* sp = reinterpret_cast<const float4*>(g_skip + (size_t)node * 64 + h * 16);
#pragma unroll
    for (int j = 0; j < 4; j++) {
        float4 t = tp[j], sk = sp[j];
        float bx = sbe[h * 16 + 4 * j + 0], by = sbe[h * 16 + 4 * j + 1];
        float bz = sbe[h * 16 + 4 * j + 2], bw = sbe[h * 16 + 4 * j + 3];
        t.x = (t.x + w[j].x + den * bx) * inv + sk.x;
        t.y = (t.y + w[j].y + den * by) * inv + sk.y;
        t.z = (t.z + w[j].z + den * bz) * inv + sk.z;
        t.w = (t.w + w[j].w + den * bw) * inv + sk.w;
        tp[j] = t;
    }
}

// ---------------- BN stats ----------------
__global__ void bn_stats_kernel(int n) {
    int tid = threadIdx.x;
    int c = tid & 63;
    int rowg = tid >> 6;
    float s = 0.0f, q = 0.0f;
    for (int r = blockIdx.x * 4 + rowg; r < n; r += gridDim.x * 4) {
        float v = g_t[(size_t)r * 64 + c];
        s += v; q += v * v;
    }
    __shared__ float ss[256], sq[256];
    ss[tid] = s; sq[tid] = q;
    __syncthreads();
    if (tid < 128) { ss[tid] += ss[tid + 128]; sq[tid] += sq[tid + 128]; }
    __syncthreads();
    if (tid < 64) {
        atomicAdd(&g_bnsum[tid], ss[tid] + ss[tid + 64]);
        atomicAdd(&g_bnsq[tid], sq[tid] + sq[tid + 64]);
    }
}

// ---------------- BN apply + GELU + residual ----------------
__global__ void bn_apply_kernel(const float* __restrict__ gamma, const float* __restrict__ beta, int n) {
    int idx = blockIdx.x * blockDim.x + threadIdx.x;
    if (idx >= n * 16) return;
    int c0 = (idx & 15) * 4;
    float invN = 1.0f / (float)n;
    float4 tv = reinterpret_cast<const float4*>(g_t)[idx];
    float4 hv = reinterpret_cast<const float4*>(g_h)[idx];
    float tt[4] = {tv.x, tv.y, tv.z, tv.w};
    float hh[4] = {hv.x, hv.y, hv.z, hv.w};
    float r[4];
#pragma unroll
    for (int k = 0; k < 4; k++) {
        int c = c0 + k;
        float mu = g_bnsum[c] * invN;
        float var = g_bnsq[c] * invN - mu * mu;
        float y = gamma[c] * (tt[k] - mu) * rsqrtf(var + 1e-5f) + beta[c];
        float gl = 0.5f * y * (1.0f + erff(y * 0.70710678118654752f));
        r[k] = gl + hh[k];
    }
    float4 o; o.x = r[0]; o.y = r[1]; o.z = r[2]; o.w = r[3];
    reinterpret_cast<float4*>(g_h)[idx] = o;
}

// ---------------- pooling ----------------
__global__ void clear_pool_kernel(int G) {
    int i = blockIdx.x * blockDim.x + threadIdx.x;
    if (i < G * 64) g_pool[i] = 0.0f;
    if (i < G) g_cnt[i] = 0.0f;
}

__global__ void pool_kernel(const int* __restrict__ batch, int n) {
    int idx = blockIdx.x * blockDim.x + threadIdx.x;
    if (idx >= n * 16) return;
    int node = idx >> 4, c4 = idx & 15;
    int g = batch[node];
    float4 v = reinterpret_cast<const float4*>(g_h)[idx];
    redAddV4(&g_pool[g * 64 + c4 * 4], v.x, v.y, v.z, v.w);
    if (c4 == 0) atomicAdd(&g_cnt[g], 1.0f);
}

// ---------------- regressor ----------------
__global__ void reg_kernel(const float* __restrict__ rw1, const float* __restrict__ rb1,
                           const float* __restrict__ rw2, const float* __restrict__ rb2,
                           float* __restrict__ out) {
    int g = blockIdx.x;
    int tid = threadIdx.x;  // 128 threads
    __shared__ float feat[128];
    __shared__ float hred[64];
    float invc = 1.0f / fmaxf(g_cnt[g], 1.0f);
    float s = g_pool[g * 64 + (tid & 63)];
    feat[tid] = (tid < 64) ? s * invc : s;
    __syncthreads();
    if (tid < 64) {
        float acc = rb1[tid];
#pragma unroll 8
        for (int i = 0; i < 128; i++) acc += feat[i] * rw1[i * 64 + tid];
        acc = fmaxf(acc, 0.0f);
        hred[tid] = acc * rw2[tid];
    }
    __syncthreads();
    if (tid < 32) {
        float v = hred[tid] + hred[tid + 32];
#pragma unroll
        for (int off = 16; off > 0; off >>= 1) v += __shfl_down_sync(0xffffffffu, v, off);
        if (tid == 0) out[g] = v + rb2[0];
    }
}

// ---------------- host orchestration ----------------
extern "C" void kernel_launch(void* const* d_in, const int* in_sizes, int n_in,
                              void* d_out, int out_size) {
    const float* x      = (const float*)d_in[0];
    const int*   ei     = (const int*)d_in[1];
    const float* eattr  = (const float*)d_in[2];
    const int*   batch  = (const int*)d_in[3];
    const float* node_w = (const float*)d_in[4];
    const float* node_b = (const float*)d_in[5];
    const float* Wq = (const float*)d_in[6];
    const float* bq = (const float*)d_in[7];
    const float* Wk = (const float*)d_in[8];
    const float* bk = (const float*)d_in[9];
    const float* Wv = (const float*)d_in[10];
    const float* bv = (const float*)d_in[11];
    const float* We = (const float*)d_in[12];
    const float* be = (const float*)d_in[13];
    const float* Ws = (const float*)d_in[14];
    const float* bs = (const float*)d_in[15];
    const float* gamma = (const float*)d_in[16];
    const float* beta  = (const float*)d_in[17];
    const float* rw1 = (const float*)d_in[18];
    const float* rb1 = (const float*)d_in[19];
    const float* rw2 = (const float*)d_in[20];
    const float* rb2 = (const float*)d_in[21];
    float* out = (float*)d_out;

    int n = in_sizes[0] / 32;   // nodes
    int e = in_sizes[2] / 16;   // edges
    int G = out_size;           // graphs
    int nb = divup(n, 1024);

    float* ph;
    cudaGetSymbolAddress((void**)&ph, g_h);

    lin32_kernel<<<divup(n, 128), 128>>>(x, node_w, node_b, ph, n);

    // Build dst-sorted edge stream (once; reused by all 3 layers)
    hist_clear_kernel<<<divup(n, 256), 256>>>(n);
    hist_kernel<<<divup(e, 256), 256>>>(ei, e);
    scan1_kernel<<<nb, 1024>>>(n);
    scan2_kernel<<<1, 32>>>(nb);
    scan3_kernel<<<nb, 1024>>>(n);
    scatter_kernel<<<divup(e, 256), 256>>>(ei, eattr, e);

    for (int l = 0; l < 3; l++) {
        const float* wq = Wq + (size_t)l * 64 * 64;
        const float* wk = Wk + (size_t)l * 64 * 64;
        const float* wv = Wv + (size_t)l * 64 * 64;
        const float* ws = Ws + (size_t)l * 64 * 64;
        const float* we = We + (size_t)l * 16 * 64;

        qkvs_kernel<<<divup(n, 64), 256>>>(ph, wq, bq + l * 64, wk, bk + l * 64,
                                           wv, bv + l * 64, ws, bs + l * 64,
                                           we, be + l * 64, n);
        edge_fused_kernel<<<divup((long long)e * 4, 256), 256>>>(e);
        finalize_attn_kernel<<<divup((long long)n * 4, 256), 256>>>(we, be + l * 64, n);
        bn_stats_kernel<<<2048, 256>>>(n);
        bn_apply_kernel<<<divup((long long)n * 16, 256), 256>>>(gamma + l * 64, beta + l * 64, n);
    }

    clear_pool_kernel<<<divup((long long)G * 64, 256), 256>>>(G);
    pool_kernel<<<divup((long long)n * 16, 256), 256>>>(batch, n);
    reg_kernel<<<G, 128>>>(rw1, rb1, rw2, rb2, out);
}

// round 10
// speedup vs baseline: 1.4160x; 1.0035x over previous
#include <cuda_runtime.h>
#include <cuda_fp16.h>
#include <math.h>
#include <stdint.h>

#define NMAX 100000
#define EMAX 1000000
#define GMAXG 512

// ---------------- scratch (device globals; no allocation allowed) ----------------
__device__ float   g_h[NMAX * 64];        // residual stream
__device__ float   g_t[NMAX * 64];        // attn accumulator / pre-BN buffer
__device__ float   g_s[NMAX * 64];        // per (node,head) sum of ex*edge_attr
__device__ __half2 g_qh[NMAX * 32];       // q fp16
__device__ __half2 g_kh[NMAX * 32];       // k fp16
__device__ __half2 g_vh[NMAX * 32];       // v fp16
__device__ __half2 g_ph[NMAX * 32];       // p_h = We_h @ q_h fp16
__device__ float   g_r[NMAX * 4];         // r_h = q_h . be_h
__device__ float   g_skip[NMAX * 64];
__device__ float   g_denom[NMAX * 4];
__device__ float   g_bnsum[64];
__device__ float   g_bnsq[64];
__device__ float   g_pool[GMAXG * 64];
__device__ float   g_cnt[GMAXG];
// CSR / sorted edge stream (built once per launch; edge list is layer-invariant)
__device__ int     g_cnt_n[NMAX];
__device__ int     g_row[NMAX + 1];
__device__ int     g_wp[NMAX];
__device__ int     g_bsum[128];
__device__ int     g_ssrc[EMAX];
__device__ int     g_sdst[EMAX];
__device__ __half2 g_seah[EMAX * 8];

static inline unsigned divup(long long a, int b) { return (unsigned)((a + b - 1) / b); }

__device__ __forceinline__ void redAddV4(float* addr, float a, float b, float c, float d) {
    asm volatile("red.global.add.v4.f32 [%0], {%1,%2,%3,%4};"
                 :: "l"(addr), "f"(a), "f"(b), "f"(c), "f"(d) : "memory");
}
__device__ __forceinline__ float2 h2f(unsigned u) {
    return __half22float2(*reinterpret_cast<const __half2*>(&u));
}
__device__ __forceinline__ unsigned f2tf32(float x) {
    unsigned r;
    asm("cvt.rna.tf32.f32 %0, %1;" : "=r"(r) : "f"(x));
    return r;
}
__device__ __forceinline__ void mma_tf32(float* d, const unsigned* a, unsigned b0, unsigned b1) {
    asm volatile(
        "mma.sync.aligned.m16n8k8.row.col.f32.tf32.tf32.f32 "
        "{%0,%1,%2,%3}, {%4,%5,%6,%7}, {%8,%9}, {%0,%1,%2,%3};"
        : "+f"(d[0]), "+f"(d[1]), "+f"(d[2]), "+f"(d[3])
        : "r"(a[0]), "r"(a[1]), "r"(a[2]), "r"(a[3]), "r"(b0), "r"(b1));
}

// ---------------- initial node linear: out[n,64] = in[n,32] @ W[32,64] + b ----------------
__global__ void lin32_kernel(const float* __restrict__ in, const float* __restrict__ W,
                             const float* __restrict__ bias, float* __restrict__ out, int n) {
    __shared__ float sW[32 * 64];
    __shared__ float sb[64];
    for (int i = threadIdx.x; i < 32 * 64; i += blockDim.x) sW[i] = W[i];
    if (threadIdx.x < 64) sb[threadIdx.x] = bias[threadIdx.x];
    __syncthreads();
    int node = blockIdx.x * blockDim.x + threadIdx.x;
    if (node >= n) return;
    float4 acc[16];
#pragma unroll
    for (int j = 0; j < 16; j++) {
        acc[j].x = sb[4 * j + 0]; acc[j].y = sb[4 * j + 1];
        acc[j].z = sb[4 * j + 2]; acc[j].w = sb[4 * j + 3];
    }
    const float4* inp = reinterpret_cast<const float4*>(in + (size_t)node * 32);
#pragma unroll
    for (int c = 0; c < 8; c++) {
        float4 x4 = inp[c];
        float xs[4] = {x4.x, x4.y, x4.z, x4.w};
#pragma unroll
        for (int kk = 0; kk < 4; kk++) {
            float x = xs[kk];
            const float4* wr = reinterpret_cast<const float4*>(&sW[(c * 4 + kk) * 64]);
#pragma unroll
            for (int j = 0; j < 16; j++) {
                float4 w = wr[j];
                acc[j].x += x * w.x; acc[j].y += x * w.y;
                acc[j].z += x * w.z; acc[j].w += x * w.w;
            }
        }
    }
    float4* op = reinterpret_cast<float4*>(out + (size_t)node * 64);
#pragma unroll
    for (int j = 0; j < 16; j++) op[j] = acc[j];
}

// ---------------- CSR build (once per launch) ----------------
__global__ void hist_clear_kernel(int n) {
    int i = blockIdx.x * blockDim.x + threadIdx.x;
    if (i < n) g_cnt_n[i] = 0;
}
__global__ void hist_kernel(const int* __restrict__ ei, int e) {
    int i = blockIdx.x * blockDim.x + threadIdx.x;
    if (i < e) atomicAdd(&g_cnt_n[ei[e + i]], 1);
}
__global__ void scan1_kernel(int n) {
    __shared__ int sm[1024];
    int i = blockIdx.x * 1024 + threadIdx.x;
    int v = (i < n) ? g_cnt_n[i] : 0;
    sm[threadIdx.x] = v;
    __syncthreads();
    for (int off = 1; off < 1024; off <<= 1) {
        int t = (threadIdx.x >= off) ? sm[threadIdx.x - off] : 0;
        __syncthreads();
        sm[threadIdx.x] += t;
        __syncthreads();
    }
    if (i < n) g_row[i + 1] = sm[threadIdx.x];
    if (threadIdx.x == 1023) g_bsum[blockIdx.x] = sm[1023];
}
__global__ void scan2_kernel(int nb) {
    if (threadIdx.x == 0) {
        int acc = 0;
        for (int b = 0; b < nb; b++) { int t = g_bsum[b]; g_bsum[b] = acc; acc += t; }
    }
}
__global__ void scan3_kernel(int n) {
    int i = blockIdx.x * 1024 + threadIdx.x;
    if (i < n) {
        int incl = g_row[i + 1] + g_bsum[blockIdx.x];
        g_row[i + 1] = incl;
        g_wp[i] = incl - g_cnt_n[i];
    }
    if (i == 0) g_row[0] = 0;
}
__global__ void scatter_kernel(const int* __restrict__ ei, const float* __restrict__ eattr, int e) {
    int eid = blockIdx.x * 256 + threadIdx.x;
    if (eid >= e) return;
    int dst = ei[e + eid];
    int pos = atomicAdd(&g_wp[dst], 1);
    g_ssrc[pos] = ei[eid];
    g_sdst[pos] = dst;
    const float4* ea = reinterpret_cast<const float4*>(eattr + (size_t)eid * 16);
    __half2 hp[8];
#pragma unroll
    for (int jj = 0; jj < 4; jj++) {
        float4 v = ea[jj];
        hp[2 * jj]     = __floats2half2_rn(v.x, v.y);
        hp[2 * jj + 1] = __floats2half2_rn(v.z, v.w);
    }
    uint4* dp = reinterpret_cast<uint4*>(g_seah + (size_t)pos * 8);
    dp[0] = *reinterpret_cast<uint4*>(&hp[0]);
    dp[1] = *reinterpret_cast<uint4*>(&hp[4]);
}

// ---------------- fused q/k/v (tf32 mma) + skip (fp32 SIMT) + p/r + clears ----------------
// block = 256 threads (8 warps) = 64 nodes. mma: warp w -> node group (w>>1)*16, col half (w&1)*32.
#define XS_STRIDE 68
#define SW_STRIDE 72
__global__ void qkvs_kernel(const float* __restrict__ h,
                            const float* __restrict__ Wq, const float* __restrict__ bq,
                            const float* __restrict__ Wk, const float* __restrict__ bk,
                            const float* __restrict__ Wv, const float* __restrict__ bv,
                            const float* __restrict__ Ws, const float* __restrict__ bs,
                            const float* __restrict__ We, const float* __restrict__ be,
                            int n) {
    __shared__ float xs[64 * XS_STRIDE];      // 17408 B
    __shared__ float sW[64 * SW_STRIDE];      // 18432 B
    __shared__ float sb[64];
    __shared__ float sWe[16 * 64];            // 4096 B
    __shared__ float sbe[64];
    __shared__ __half qbuf[64 * 64];          // 8192 B
    const int tid = threadIdx.x;
    const int base = blockIdx.x * 64;

    if (blockIdx.x == 0 && tid < 64) { g_bnsum[tid] = 0.0f; g_bnsq[tid] = 0.0f; }

    // clear this block's slice of t/s/denom
    {
        float4 z; z.x = 0.f; z.y = 0.f; z.z = 0.f; z.w = 0.f;
        int lim = n * 16;
        for (int i = tid; i < 1024; i += 256) {
            int gi = base * 16 + i;
            if (gi < lim) {
                reinterpret_cast<float4*>(g_t)[gi] = z;
                reinterpret_cast<float4*>(g_s)[gi] = z;
            }
        }
        if (tid < 64 && base + tid < n) reinterpret_cast<float4*>(g_denom)[base + tid] = z;
    }

    for (int idx = tid; idx < 64 * 16; idx += 256) {
        int nl = idx >> 4, kk = idx & 15;
        int gn = base + nl;
        if (gn < n) {
            float4 x4 = reinterpret_cast<const float4*>(h + (size_t)gn * 64)[kk];
            float* p = &xs[nl * XS_STRIDE + kk * 4];
            p[0] = x4.x; p[1] = x4.y; p[2] = x4.z; p[3] = x4.w;
        }
    }
    for (int i = tid; i < 1024; i += 256) sWe[i] = We[i];
    if (tid < 64) sbe[tid] = be[tid];

    const float* Wm[4] = {Wq, Wk, Wv, Ws};
    const float* bm[4] = {bq, bk, bv, bs};

    const int warp = tid >> 5, lane = tid & 31;
    const int g4 = warp >> 1;             // node group (16 nodes)
    const int chalf = warp & 1;           // column half (32 cols)
    const int grp = lane >> 2;            // 0..7
    const int qd = lane & 3;              // 0..3
    const int nl = tid & 63;
    const int quart = tid >> 6;           // head index for skip / p / r
    const int gn = base + nl;

    for (int m = 0; m < 4; m++) {
        __syncthreads();
        {
            const float* wsrc = Wm[m];
            for (int i = tid; i < 4096; i += 256) {
                float w = wsrc[i];
                if (m < 3) w = __uint_as_float(f2tf32(w));   // pre-round B to tf32
                sW[(i >> 6) * SW_STRIDE + (i & 63)] = w;
            }
            if (tid < 64) sb[tid] = bm[m][tid];
        }
        __syncthreads();

        if (m < 3) {
            // ---- tensor-core path: rows g4*16..+15, cols chalf*32..+31 ----
            float acc[4][4];
#pragma unroll
            for (int t = 0; t < 4; t++)
#pragma unroll
                for (int d = 0; d < 4; d++) acc[t][d] = 0.0f;

#pragma unroll
            for (int ks = 0; ks < 8; ks++) {
                unsigned a[4];
                const float* xr = &xs[(g4 * 16 + grp) * XS_STRIDE + ks * 8 + qd];
                a[0] = f2tf32(xr[0]);
                a[2] = f2tf32(xr[4]);
                a[1] = f2tf32(xr[8 * XS_STRIDE]);
                a[3] = f2tf32(xr[8 * XS_STRIDE + 4]);
#pragma unroll
                for (int t = 0; t < 4; t++) {
                    int cb = chalf * 32 + t * 8;
                    unsigned b0 = __float_as_uint(sW[(ks * 8 + qd) * SW_STRIDE + cb + grp]);
                    unsigned b1 = __float_as_uint(sW[(ks * 8 + qd + 4) * SW_STRIDE + cb + grp]);
                    mma_tf32(acc[t], a, b0, b1);
                }
            }
            // epilogue: add bias, convert to fp16, store
            int r0 = g4 * 16 + grp;
#pragma unroll
            for (int t = 0; t < 4; t++) {
                int col = chalf * 32 + t * 8 + qd * 2;
                __half2 hlo = __floats2half2_rn(acc[t][0] + sb[col], acc[t][1] + sb[col + 1]);
                __half2 hhi = __floats2half2_rn(acc[t][2] + sb[col], acc[t][3] + sb[col + 1]);
                if (m == 0) {
                    *reinterpret_cast<__half2*>(&qbuf[r0 * 64 + col]) = hlo;
                    *reinterpret_cast<__half2*>(&qbuf[(r0 + 8) * 64 + col]) = hhi;
                } else {
                    __half2* dst = (m == 1) ? g_kh : g_vh;
                    if (base + r0 < n)     dst[(size_t)(base + r0) * 32 + (col >> 1)] = hlo;
                    if (base + r0 + 8 < n) dst[(size_t)(base + r0 + 8) * 32 + (col >> 1)] = hhi;
                }
            }
            if (m == 0) {
                __syncthreads();
                if (gn < n) {
                    // q for (node nl, head quart) from qbuf; write g_qh, compute p/r
                    uint4 u0 = *reinterpret_cast<const uint4*>(&qbuf[nl * 64 + quart * 16]);
                    uint4 u1 = *reinterpret_cast<const uint4*>(&qbuf[nl * 64 + quart * 16 + 8]);
                    uint4* qp = reinterpret_cast<uint4*>(g_qh + (size_t)gn * 32 + quart * 8);
                    qp[0] = u0; qp[1] = u1;
                    float qv[16];
                    {
                        const unsigned* uw = reinterpret_cast<const unsigned*>(&u0);
#pragma unroll
                        for (int j = 0; j < 4; j++) {
                            float2 f = h2f(uw[j]); qv[2 * j] = f.x; qv[2 * j + 1] = f.y;
                        }
                        const unsigned* uw1 = reinterpret_cast<const unsigned*>(&u1);
#pragma unroll
                        for (int j = 0; j < 4; j++) {
                            float2 f = h2f(uw1[j]); qv[8 + 2 * j] = f.x; qv[9 + 2 * j] = f.y;
                        }
                    }
                    float pc[16];
#pragma unroll
                    for (int c = 0; c < 16; c++) {
                        const float4* wr = reinterpret_cast<const float4*>(&sWe[c * 64 + quart * 16]);
                        float s = 0.0f;
#pragma unroll
                        for (int j = 0; j < 4; j++) {
                            float4 w = wr[j];
                            s += w.x * qv[4 * j] + w.y * qv[4 * j + 1]
                               + w.z * qv[4 * j + 2] + w.w * qv[4 * j + 3];
                        }
                        pc[c] = s;
                    }
                    float rr = 0.0f;
#pragma unroll
                    for (int d = 0; d < 16; d++) rr += sbe[quart * 16 + d] * qv[d];
                    __half2 hp[8];
#pragma unroll
                    for (int j = 0; j < 8; j++) hp[j] = __floats2half2_rn(pc[2 * j], pc[2 * j + 1]);
                    uint4* pp = reinterpret_cast<uint4*>(g_ph + (size_t)gn * 32 + quart * 8);
                    pp[0] = *reinterpret_cast<uint4*>(&hp[0]);
                    pp[1] = *reinterpret_cast<uint4*>(&hp[4]);
                    g_r[gn * 4 + quart] = rr;
                }
            }
        } else if (gn < n) {
            // ---- skip path: fp32 SIMT, thread = (node nl, 16 cols of quart) ----
            float4 acc[4];
#pragma unroll
            for (int j = 0; j < 4; j++) {
                acc[j].x = sb[quart * 16 + 4 * j + 0];
                acc[j].y = sb[quart * 16 + 4 * j + 1];
                acc[j].z = sb[quart * 16 + 4 * j + 2];
                acc[j].w = sb[quart * 16 + 4 * j + 3];
            }
            const float* xrow = &xs[nl * XS_STRIDE];
#pragma unroll 8
            for (int k = 0; k < 64; k++) {
                float x = xrow[k];
                const float4* wr = reinterpret_cast<const float4*>(&sW[k * SW_STRIDE + quart * 16]);
#pragma unroll
                for (int j = 0; j < 4; j++) {
                    float4 w = wr[j];
                    acc[j].x += x * w.x; acc[j].y += x * w.y;
                    acc[j].z += x * w.z; acc[j].w += x * w.w;
                }
            }
            float4* op = reinterpret_cast<float4*>(g_skip + (size_t)gn * 64 + quart * 16);
#pragma unroll
            for (int j = 0; j < 4; j++) op[j] = acc[j];
        }
    }
}

// ---------------- single fused edge pass over the dst-sorted edge stream ----------------
__global__ void edge_fused_kernel(int e) {
    int idx = blockIdx.x * 256 + threadIdx.x;
    if (idx >= e * 4) return;
    int eix = idx >> 2, j = idx & 3;
    int src = g_ssrc[eix];
    int dst = g_sdst[eix];

    uint2 eaw = *reinterpret_cast<const uint2*>(g_seah + (size_t)eix * 8 + j * 2);
    float2 ea0 = h2f(eaw.x), ea1 = h2f(eaw.y);

    const uint2* qb = reinterpret_cast<const uint2*>(g_qh + (size_t)dst * 32 + j * 2);
    const uint2* kb = reinterpret_cast<const uint2*>(g_kh + (size_t)src * 32 + j * 2);
    const uint2* pb = reinterpret_cast<const uint2*>(g_ph + (size_t)dst * 32 + j * 2);

    float part[4];
#pragma unroll
    for (int i = 0; i < 4; i++) {
        uint2 qr = qb[i * 4];
        uint2 kr = kb[i * 4];
        uint2 pr = pb[i * 4];
        float2 q0 = h2f(qr.x), q1 = h2f(qr.y);
        float2 k0 = h2f(kr.x), k1 = h2f(kr.y);
        float2 p0 = h2f(pr.x), p1 = h2f(pr.y);
        part[i] = q0.x * k0.x + q0.y * k0.y + q1.x * k1.x + q1.y * k1.y
                + p0.x * ea0.x + p0.y * ea0.y + p1.x * ea1.x + p1.y * ea1.y;
    }
    part[j] += g_r[dst * 4 + j];

    unsigned lane = threadIdx.x & 31;
    unsigned gmask = 0xFu << (lane & 28);
#pragma unroll
    for (int off = 1; off < 4; off <<= 1) {
#pragma unroll
        for (int i = 0; i < 4; i++) part[i] += __shfl_xor_sync(gmask, part[i], off);
    }

    float ex[4];
#pragma unroll
    for (int i = 0; i < 4; i++) ex[i] = __expf(part[i] * 0.25f);

    if (j == 0) redAddV4(&g_denom[dst * 4], ex[0], ex[1], ex[2], ex[3]);

    const uint2* vb = reinterpret_cast<const uint2*>(g_vh + (size_t)src * 32 + j * 2);
    float* tb = g_t + (size_t)dst * 64 + j * 4;
    float* sb = g_s + (size_t)dst * 64 + j * 4;
#pragma unroll
    for (int i = 0; i < 4; i++) {
        uint2 vr = vb[i * 4];
        float2 v0 = h2f(vr.x), v1 = h2f(vr.y);
        redAddV4(tb + i * 16, ex[i] * v0.x, ex[i] * v0.y, ex[i] * v1.x, ex[i] * v1.y);
        redAddV4(sb + i * 16, ex[i] * ea0.x, ex[i] * ea0.y, ex[i] * ea1.x, ex[i] * ea1.y);
    }
}

// ---------------- finalize: t = (t + We_h^T s + denom*be_h)/(denom+1e-16) + skip ----------------
__global__ void finalize_attn_kernel(const float* __restrict__ We, const float* __restrict__ be, int n) {
    __shared__ float sWe[16 * 64];
    __shared__ float sbe[64];
    const int tid = threadIdx.x;
    for (int i = tid; i < 1024; i += 256) sWe[i] = We[i];
    if (tid < 64) sbe[tid] = be[tid];
    __syncthreads();

    int idx = blockIdx.x * 256 + tid;
    if (idx >= n * 4) return;
    int node = idx >> 2, h = idx & 3;
    float den = g_denom[idx];
    float inv = 1.0f / (den + 1e-16f);

    const float4* sv = reinterpret_cast<const float4*>(g_s + (size_t)node * 64 + h * 16);
    float sarr[16];
#pragma unroll
    for (int j = 0; j < 4; j++) {
        float4 s4 = sv[j];
        sarr[4 * j] = s4.x; sarr[4 * j + 1] = s4.y; sarr[4 * j + 2] = s4.z; sarr[4 * j + 3] = s4.w;
    }
    float4 w[4];
#pragma unroll
    for (int j = 0; j < 4; j++) { w[j].x = 0.f; w[j].y = 0.f; w[j].z = 0.f; w[j].w = 0.f; }
#pragma unroll
    for (int c = 0; c < 16; c++) {
        float sc = sarr[c];
        const float4* wr = reinterpret_cast<const float4*>(&sWe[c * 64 + h * 16]);
#pragma unroll
        for (int j = 0; j < 4; j++) {
            float4 ww = wr[j];
            w[j].x += sc * ww.x; w[j].y += sc * ww.y;
            w[j].z += sc * ww.z; w[j].w += sc * ww.w;
        }
    }
    float4* tp = reinterpret_cast<float4*>(g_t + (size_t)node * 64 + h * 16);
    const float4* sp = reinterpret_cast<const float4*>(g_skip + (size_t)node * 64 + h * 16);
#pragma unroll
    for (int j = 0; j < 4; j++) {
        float4 t = tp[j], sk = sp[j];
        float bx = sbe[h * 16 + 4 * j + 0], by = sbe[h * 16 + 4 * j + 1];
        float bz = sbe[h * 16 + 4 * j + 2], bw = sbe[h * 16 + 4 * j + 3];
        t.x = (t.x + w[j].x + den * bx) * inv + sk.x;
        t.y = (t.y + w[j].y + den * by) * inv + sk.y;
        t.z = (t.z + w[j].z + den * bz) * inv + sk.z;
        t.w = (t.w + w[j].w + den * bw) * inv + sk.w;
        tp[j] = t;
    }
}

// ---------------- BN stats ----------------
__global__ void bn_stats_kernel(int n) {
    int tid = threadIdx.x;
    int c = tid & 63;
    int rowg = tid >> 6;
    float s = 0.0f, q = 0.0f;
    for (int r = blockIdx.x * 4 + rowg; r < n; r += gridDim.x * 4) {
        float v = g_t[(size_t)r * 64 + c];
        s += v; q += v * v;
    }
    __shared__ float ss[256], sq[256];
    ss[tid] = s; sq[tid] = q;
    __syncthreads();
    if (tid < 128) { ss[tid] += ss[tid + 128]; sq[tid] += sq[tid + 128]; }
    __syncthreads();
    if (tid < 64) {
        atomicAdd(&g_bnsum[tid], ss[tid] + ss[tid + 64]);
        atomicAdd(&g_bnsq[tid], sq[tid] + sq[tid + 64]);
    }
}

// ---------------- BN apply + GELU + residual ----------------
__global__ void bn_apply_kernel(const float* __restrict__ gamma, const float* __restrict__ beta, int n) {
    int idx = blockIdx.x * blockDim.x + threadIdx.x;
    if (idx >= n * 16) return;
    int c0 = (idx & 15) * 4;
    float invN = 1.0f / (float)n;
    float4 tv = reinterpret_cast<const float4*>(g_t)[idx];
    float4 hv = reinterpret_cast<const float4*>(g_h)[idx];
    float tt[4] = {tv.x, tv.y, tv.z, tv.w};
    float hh[4] = {hv.x, hv.y, hv.z, hv.w};
    float r[4];
#pragma unroll
    for (int k = 0; k < 4; k++) {
        int c = c0 + k;
        float mu = g_bnsum[c] * invN;
        float var = g_bnsq[c] * invN - mu * mu;
        float y = gamma[c] * (tt[k] - mu) * rsqrtf(var + 1e-5f) + beta[c];
        float gl = 0.5f * y * (1.0f + erff(y * 0.70710678118654752f));
        r[k] = gl + hh[k];
    }
    float4 o; o.x = r[0]; o.y = r[1]; o.z = r[2]; o.w = r[3];
    reinterpret_cast<float4*>(g_h)[idx] = o;
}

// ---------------- pooling ----------------
__global__ void clear_pool_kernel(int G) {
    int i = blockIdx.x * blockDim.x + threadIdx.x;
    if (i < G * 64) g_pool[i] = 0.0f;
    if (i < G) g_cnt[i] = 0.0f;
}

__global__ void pool_kernel(const int* __restrict__ batch, int n) {
    int idx = blockIdx.x * blockDim.x + threadIdx.x;
    if (idx >= n * 16) return;
    int node = idx >> 4, c4 = idx & 15;
    int g = batch[node];
    float4 v = reinterpret_cast<const float4*>(g_h)[idx];
    redAddV4(&g_pool[g * 64 + c4 * 4], v.x, v.y, v.z, v.w);
    if (c4 == 0) atomicAdd(&g_cnt[g], 1.0f);
}

// ---------------- regressor ----------------
__global__ void reg_kernel(const float* __restrict__ rw1, const float* __restrict__ rb1,
                           const float* __restrict__ rw2, const float* __restrict__ rb2,
                           float* __restrict__ out) {
    int g = blockIdx.x;
    int tid = threadIdx.x;  // 128 threads
    __shared__ float feat[128];
    __shared__ float hred[64];
    float invc = 1.0f / fmaxf(g_cnt[g], 1.0f);
    float s = g_pool[g * 64 + (tid & 63)];
    feat[tid] = (tid < 64) ? s * invc : s;
    __syncthreads();
    if (tid < 64) {
        float acc = rb1[tid];
#pragma unroll 8
        for (int i = 0; i < 128; i++) acc += feat[i] * rw1[i * 64 + tid];
        acc = fmaxf(acc, 0.0f);
        hred[tid] = acc * rw2[tid];
    }
    __syncthreads();
    if (tid < 32) {
        float v = hred[tid] + hred[tid + 32];
#pragma unroll
        for (int off = 16; off > 0; off >>= 1) v += __shfl_down_sync(0xffffffffu, v, off);
        if (tid == 0) out[g] = v + rb2[0];
    }
}

// ---------------- host orchestration ----------------
extern "C" void kernel_launch(void* const* d_in, const int* in_sizes, int n_in,
                              void* d_out, int out_size) {
    const float* x      = (const float*)d_in[0];
    const int*   ei     = (const int*)d_in[1];
    const float* eattr  = (const float*)d_in[2];
    const int*   batch  = (const int*)d_in[3];
    const float* node_w = (const float*)d_in[4];
    const float* node_b = (const float*)d_in[5];
    const float* Wq = (const float*)d_in[6];
    const float* bq = (const float*)d_in[7];
    const float* Wk = (const float*)d_in[8];
    const float* bk = (const float*)d_in[9];
    const float* Wv = (const float*)d_in[10];
    const float* bv = (const float*)d_in[11];
    const float* We = (const float*)d_in[12];
    const float* be = (const float*)d_in[13];
    const float* Ws = (const float*)d_in[14];
    const float* bs = (const float*)d_in[15];
    const float* gamma = (const float*)d_in[16];
    const float* beta  = (const float*)d_in[17];
    const float* rw1 = (const float*)d_in[18];
    const float* rb1 = (const float*)d_in[19];
    const float* rw2 = (const float*)d_in[20];
    const float* rb2 = (const float*)d_in[21];
    float* out = (float*)d_out;

    int n = in_sizes[0] / 32;   // nodes
    int e = in_sizes[2] / 16;   // edges
    int G = out_size;           // graphs
    int nb = divup(n, 1024);

    float* ph;
    cudaGetSymbolAddress((void**)&ph, g_h);

    lin32_kernel<<<divup(n, 128), 128>>>(x, node_w, node_b, ph, n);

    // Build dst-sorted edge stream (once; reused by all 3 layers)
    hist_clear_kernel<<<divup(n, 256), 256>>>(n);
    hist_kernel<<<divup(e, 256), 256>>>(ei, e);
    scan1_kernel<<<nb, 1024>>>(n);
    scan2_kernel<<<1, 32>>>(nb);
    scan3_kernel<<<nb, 1024>>>(n);
    scatter_kernel<<<divup(e, 256), 256>>>(ei, eattr, e);

    for (int l = 0; l < 3; l++) {
        const float* wq = Wq + (size_t)l * 64 * 64;
        const float* wk = Wk + (size_t)l * 64 * 64;
        const float* wv = Wv + (size_t)l * 64 * 64;
        const float* ws = Ws + (size_t)l * 64 * 64;
        const float* we = We + (size_t)l * 16 * 64;

        qkvs_kernel<<<divup(n, 64), 256>>>(ph, wq, bq + l * 64, wk, bk + l * 64,
                                           wv, bv + l * 64, ws, bs + l * 64,
                                           we, be + l * 64, n);
        edge_fused_kernel<<<divup((long long)e * 4, 256), 256>>>(e);
        finalize_attn_kernel<<<divup((long long)n * 4, 256), 256>>>(we, be + l * 64, n);
        bn_stats_kernel<<<2048, 256>>>(n);
        bn_apply_kernel<<<divup((long long)n * 16, 256), 256>>>(gamma + l * 64, beta + l * 64, n);
    }

    clear_pool_kernel<<<divup((long long)G * 64, 256), 256>>>(G);
    pool_kernel<<<divup((long long)n * 16, 256), 256>>>(batch, n);
    reg_kernel<<<G, 128>>>(rw1, rb1, rw2, rb2, out);
}

// round 11
// speedup vs baseline: 1.5390x; 1.0868x over previous
#include <cuda_runtime.h>
#include <cuda_fp16.h>
#include <math.h>
#include <stdint.h>

#define NMAX 100000
#define EMAX 1000000
#define GMAXG 512

// ---------------- scratch (device globals; no allocation allowed) ----------------
__device__ float   g_h[NMAX * 64];        // residual stream
__device__ float   g_t[NMAX * 64];        // attn accumulator / pre-BN buffer
__device__ float   g_s[NMAX * 64];        // per (node,head) sum of ex*edge_attr
__device__ __half2 g_qh[NMAX * 32];       // q fp16
__device__ __half2 g_kh[NMAX * 32];       // k fp16
__device__ __half2 g_vh[NMAX * 32];       // v fp16
__device__ __half2 g_ph[NMAX * 32];       // p_h = We_h @ q_h fp16
__device__ float   g_r[NMAX * 4];         // r_h = q_h . be_h
__device__ float   g_skip[NMAX * 64];
__device__ float   g_denom[NMAX * 4];
__device__ float   g_bnsum[64];
__device__ float   g_bnsq[64];
__device__ float   g_pool[GMAXG * 64];
__device__ float   g_cnt[GMAXG];
// CSR / sorted edge stream (built once per launch; edge list is layer-invariant)
__device__ int     g_cnt_n[NMAX];
__device__ int     g_row[NMAX + 1];
__device__ int     g_wp[NMAX];
__device__ int     g_bsum[128];
__device__ int     g_ssrc[EMAX];
__device__ __half2 g_seah[EMAX * 8];

static inline unsigned divup(long long a, int b) { return (unsigned)((a + b - 1) / b); }

__device__ __forceinline__ void redAddV4(float* addr, float a, float b, float c, float d) {
    asm volatile("red.global.add.v4.f32 [%0], {%1,%2,%3,%4};"
                 :: "l"(addr), "f"(a), "f"(b), "f"(c), "f"(d) : "memory");
}
__device__ __forceinline__ float2 h2f(unsigned u) {
    return __half22float2(*reinterpret_cast<const __half2*>(&u));
}
__device__ __forceinline__ unsigned f2tf32(float x) {
    unsigned r;
    asm("cvt.rna.tf32.f32 %0, %1;" : "=r"(r) : "f"(x));
    return r;
}
__device__ __forceinline__ void mma_tf32(float* d, const unsigned* a, unsigned b0, unsigned b1) {
    asm volatile(
        "mma.sync.aligned.m16n8k8.row.col.f32.tf32.tf32.f32 "
        "{%0,%1,%2,%3}, {%4,%5,%6,%7}, {%8,%9}, {%0,%1,%2,%3};"
        : "+f"(d[0]), "+f"(d[1]), "+f"(d[2]), "+f"(d[3])
        : "r"(a[0]), "r"(a[1]), "r"(a[2]), "r"(a[3]), "r"(b0), "r"(b1));
}

// ---------------- initial node linear: out[n,64] = in[n,32] @ W[32,64] + b ----------------
__global__ void lin32_kernel(const float* __restrict__ in, const float* __restrict__ W,
                             const float* __restrict__ bias, float* __restrict__ out, int n) {
    __shared__ float sW[32 * 64];
    __shared__ float sb[64];
    for (int i = threadIdx.x; i < 32 * 64; i += blockDim.x) sW[i] = W[i];
    if (threadIdx.x < 64) sb[threadIdx.x] = bias[threadIdx.x];
    __syncthreads();
    int node = blockIdx.x * blockDim.x + threadIdx.x;
    if (node >= n) return;
    float4 acc[16];
#pragma unroll
    for (int j = 0; j < 16; j++) {
        acc[j].x = sb[4 * j + 0]; acc[j].y = sb[4 * j + 1];
        acc[j].z = sb[4 * j + 2]; acc[j].w = sb[4 * j + 3];
    }
    const float4* inp = reinterpret_cast<const float4*>(in + (size_t)node * 32);
#pragma unroll
    for (int c = 0; c < 8; c++) {
        float4 x4 = inp[c];
        float xs[4] = {x4.x, x4.y, x4.z, x4.w};
#pragma unroll
        for (int kk = 0; kk < 4; kk++) {
            float x = xs[kk];
            const float4* wr = reinterpret_cast<const float4*>(&sW[(c * 4 + kk) * 64]);
#pragma unroll
            for (int j = 0; j < 16; j++) {
                float4 w = wr[j];
                acc[j].x += x * w.x; acc[j].y += x * w.y;
                acc[j].z += x * w.z; acc[j].w += x * w.w;
            }
        }
    }
    float4* op = reinterpret_cast<float4*>(out + (size_t)node * 64);
#pragma unroll
    for (int j = 0; j < 16; j++) op[j] = acc[j];
}

// ---------------- CSR build (once per launch) ----------------
__global__ void hist_clear_kernel(int n) {
    int i = blockIdx.x * blockDim.x + threadIdx.x;
    if (i < n) g_cnt_n[i] = 0;
}
__global__ void hist_kernel(const int* __restrict__ ei, int e) {
    int i = blockIdx.x * blockDim.x + threadIdx.x;
    if (i < e) atomicAdd(&g_cnt_n[ei[e + i]], 1);
}
__global__ void scan1_kernel(int n) {
    __shared__ int sm[1024];
    int i = blockIdx.x * 1024 + threadIdx.x;
    int v = (i < n) ? g_cnt_n[i] : 0;
    sm[threadIdx.x] = v;
    __syncthreads();
    for (int off = 1; off < 1024; off <<= 1) {
        int t = (threadIdx.x >= off) ? sm[threadIdx.x - off] : 0;
        __syncthreads();
        sm[threadIdx.x] += t;
        __syncthreads();
    }
    if (i < n) g_row[i + 1] = sm[threadIdx.x];
    if (threadIdx.x == 1023) g_bsum[blockIdx.x] = sm[1023];
}
__global__ void scan2_kernel(int nb) {
    if (threadIdx.x == 0) {
        int acc = 0;
        for (int b = 0; b < nb; b++) { int t = g_bsum[b]; g_bsum[b] = acc; acc += t; }
    }
}
__global__ void scan3_kernel(int n) {
    int i = blockIdx.x * 1024 + threadIdx.x;
    if (i < n) {
        int incl = g_row[i + 1] + g_bsum[blockIdx.x];
        g_row[i + 1] = incl;
        g_wp[i] = incl - g_cnt_n[i];
    }
    if (i == 0) g_row[0] = 0;
}
__global__ void scatter_kernel(const int* __restrict__ ei, const float* __restrict__ eattr, int e) {
    int eid = blockIdx.x * 256 + threadIdx.x;
    if (eid >= e) return;
    int dst = ei[e + eid];
    int pos = atomicAdd(&g_wp[dst], 1);
    g_ssrc[pos] = ei[eid];
    const float4* ea = reinterpret_cast<const float4*>(eattr + (size_t)eid * 16);
    __half2 hp[8];
#pragma unroll
    for (int jj = 0; jj < 4; jj++) {
        float4 v = ea[jj];
        hp[2 * jj]     = __floats2half2_rn(v.x, v.y);
        hp[2 * jj + 1] = __floats2half2_rn(v.z, v.w);
    }
    uint4* dp = reinterpret_cast<uint4*>(g_seah + (size_t)pos * 8);
    dp[0] = *reinterpret_cast<uint4*>(&hp[0]);
    dp[1] = *reinterpret_cast<uint4*>(&hp[4]);
}

// ---------------- fused q/k/v (tf32 mma) + skip (fp32 SIMT) + p/r ----------------
// block = 256 threads (8 warps) = 64 nodes. mma: warp w -> node group (w>>1)*16, col half (w&1)*32.
#define XS_STRIDE 68
#define SW_STRIDE 72
__global__ void qkvs_kernel(const float* __restrict__ h,
                            const float* __restrict__ Wq, const float* __restrict__ bq,
                            const float* __restrict__ Wk, const float* __restrict__ bk,
                            const float* __restrict__ Wv, const float* __restrict__ bv,
                            const float* __restrict__ Ws, const float* __restrict__ bs,
                            const float* __restrict__ We, const float* __restrict__ be,
                            int n) {
    __shared__ float xs[64 * XS_STRIDE];
    __shared__ float sW[64 * SW_STRIDE];
    __shared__ float sb[64];
    __shared__ float sWe[16 * 64];
    __shared__ float sbe[64];
    __shared__ __half qbuf[64 * 64];
    const int tid = threadIdx.x;
    const int base = blockIdx.x * 64;

    if (blockIdx.x == 0 && tid < 64) { g_bnsum[tid] = 0.0f; g_bnsq[tid] = 0.0f; }

    for (int idx = tid; idx < 64 * 16; idx += 256) {
        int nl = idx >> 4, kk = idx & 15;
        int gn = base + nl;
        if (gn < n) {
            float4 x4 = reinterpret_cast<const float4*>(h + (size_t)gn * 64)[kk];
            float* p = &xs[nl * XS_STRIDE + kk * 4];
            p[0] = x4.x; p[1] = x4.y; p[2] = x4.z; p[3] = x4.w;
        }
    }
    for (int i = tid; i < 1024; i += 256) sWe[i] = We[i];
    if (tid < 64) sbe[tid] = be[tid];

    const float* Wm[4] = {Wq, Wk, Wv, Ws};
    const float* bm[4] = {bq, bk, bv, bs};

    const int warp = tid >> 5, lane = tid & 31;
    const int g4 = warp >> 1;
    const int chalf = warp & 1;
    const int grp = lane >> 2;
    const int qd = lane & 3;
    const int nl = tid & 63;
    const int quart = tid >> 6;
    const int gn = base + nl;

    for (int m = 0; m < 4; m++) {
        __syncthreads();
        {
            const float* wsrc = Wm[m];
            for (int i = tid; i < 4096; i += 256) {
                float w = wsrc[i];
                if (m < 3) w = __uint_as_float(f2tf32(w));
                sW[(i >> 6) * SW_STRIDE + (i & 63)] = w;
            }
            if (tid < 64) sb[tid] = bm[m][tid];
        }
        __syncthreads();

        if (m < 3) {
            float acc[4][4];
#pragma unroll
            for (int t = 0; t < 4; t++)
#pragma unroll
                for (int d = 0; d < 4; d++) acc[t][d] = 0.0f;

#pragma unroll
            for (int ks = 0; ks < 8; ks++) {
                unsigned a[4];
                const float* xr = &xs[(g4 * 16 + grp) * XS_STRIDE + ks * 8 + qd];
                a[0] = f2tf32(xr[0]);
                a[2] = f2tf32(xr[4]);
                a[1] = f2tf32(xr[8 * XS_STRIDE]);
                a[3] = f2tf32(xr[8 * XS_STRIDE + 4]);
#pragma unroll
                for (int t = 0; t < 4; t++) {
                    int cb = chalf * 32 + t * 8;
                    unsigned b0 = __float_as_uint(sW[(ks * 8 + qd) * SW_STRIDE + cb + grp]);
                    unsigned b1 = __float_as_uint(sW[(ks * 8 + qd + 4) * SW_STRIDE + cb + grp]);
                    mma_tf32(acc[t], a, b0, b1);
                }
            }
            int r0 = g4 * 16 + grp;
#pragma unroll
            for (int t = 0; t < 4; t++) {
                int col = chalf * 32 + t * 8 + qd * 2;
                __half2 hlo = __floats2half2_rn(acc[t][0] + sb[col], acc[t][1] + sb[col + 1]);
                __half2 hhi = __floats2half2_rn(acc[t][2] + sb[col], acc[t][3] + sb[col + 1]);
                if (m == 0) {
                    *reinterpret_cast<__half2*>(&qbuf[r0 * 64 + col]) = hlo;
                    *reinterpret_cast<__half2*>(&qbuf[(r0 + 8) * 64 + col]) = hhi;
                } else {
                    __half2* dst = (m == 1) ? g_kh : g_vh;
                    if (base + r0 < n)     dst[(size_t)(base + r0) * 32 + (col >> 1)] = hlo;
                    if (base + r0 + 8 < n) dst[(size_t)(base + r0 + 8) * 32 + (col >> 1)] = hhi;
                }
            }
            if (m == 0) {
                __syncthreads();
                if (gn < n) {
                    uint4 u0 = *reinterpret_cast<const uint4*>(&qbuf[nl * 64 + quart * 16]);
                    uint4 u1 = *reinterpret_cast<const uint4*>(&qbuf[nl * 64 + quart * 16 + 8]);
                    uint4* qp = reinterpret_cast<uint4*>(g_qh + (size_t)gn * 32 + quart * 8);
                    qp[0] = u0; qp[1] = u1;
                    float qv[16];
                    {
                        const unsigned* uw = reinterpret_cast<const unsigned*>(&u0);
#pragma unroll
                        for (int j = 0; j < 4; j++) {
                            float2 f = h2f(uw[j]); qv[2 * j] = f.x; qv[2 * j + 1] = f.y;
                        }
                        const unsigned* uw1 = reinterpret_cast<const unsigned*>(&u1);
#pragma unroll
                        for (int j = 0; j < 4; j++) {
                            float2 f = h2f(uw1[j]); qv[8 + 2 * j] = f.x; qv[9 + 2 * j] = f.y;
                        }
                    }
                    float pc[16];
#pragma unroll
                    for (int c = 0; c < 16; c++) {
                        const float4* wr = reinterpret_cast<const float4*>(&sWe[c * 64 + quart * 16]);
                        float s = 0.0f;
#pragma unroll
                        for (int j = 0; j < 4; j++) {
                            float4 w = wr[j];
                            s += w.x * qv[4 * j] + w.y * qv[4 * j + 1]
                               + w.z * qv[4 * j + 2] + w.w * qv[4 * j + 3];
                        }
                        pc[c] = s;
                    }
                    float rr = 0.0f;
#pragma unroll
                    for (int d = 0; d < 16; d++) rr += sbe[quart * 16 + d] * qv[d];
                    __half2 hp[8];
#pragma unroll
                    for (int j = 0; j < 8; j++) hp[j] = __floats2half2_rn(pc[2 * j], pc[2 * j + 1]);
                    uint4* pp = reinterpret_cast<uint4*>(g_ph + (size_t)gn * 32 + quart * 8);
                    pp[0] = *reinterpret_cast<uint4*>(&hp[0]);
                    pp[1] = *reinterpret_cast<uint4*>(&hp[4]);
                    g_r[gn * 4 + quart] = rr;
                }
            }
        } else if (gn < n) {
            float4 acc[4];
#pragma unroll
            for (int j = 0; j < 4; j++) {
                acc[j].x = sb[quart * 16 + 4 * j + 0];
                acc[j].y = sb[quart * 16 + 4 * j + 1];
                acc[j].z = sb[quart * 16 + 4 * j + 2];
                acc[j].w = sb[quart * 16 + 4 * j + 3];
            }
            const float* xrow = &xs[nl * XS_STRIDE];
#pragma unroll 8
            for (int k = 0; k < 64; k++) {
                float x = xrow[k];
                const float4* wr = reinterpret_cast<const float4*>(&sW[k * SW_STRIDE + quart * 16]);
#pragma unroll
                for (int j = 0; j < 4; j++) {
                    float4 w = wr[j];
                    acc[j].x += x * w.x; acc[j].y += x * w.y;
                    acc[j].z += x * w.z; acc[j].w += x * w.w;
                }
            }
            float4* op = reinterpret_cast<float4*>(g_skip + (size_t)gn * 64 + quart * 16);
#pragma unroll
            for (int j = 0; j < 4; j++) op[j] = acc[j];
        }
    }
}

// ---------------- edge aggregation: 4 lanes per node walk its CSR range; zero atomics ----------------
__global__ void edge_agg_kernel(int n) {
    int idx = blockIdx.x * 256 + threadIdx.x;   // (node, j)
    if (idx >= n * 4) return;
    const int node = idx >> 2, j = idx & 3;
    const unsigned lane = threadIdx.x & 31;
    const unsigned gmask = 0xFu << (lane & 28);

    // dst-side operands, loaded once per node
    const uint2* qb = reinterpret_cast<const uint2*>(g_qh + (size_t)node * 32 + j * 2);
    const uint2* pb = reinterpret_cast<const uint2*>(g_ph + (size_t)node * 32 + j * 2);
    uint2 qv[4], pv[4];
#pragma unroll
    for (int i = 0; i < 4; i++) { qv[i] = qb[i * 4]; pv[i] = pb[i * 4]; }
    const float rj = g_r[node * 4 + j];

    const int rs = g_row[node], re = g_row[node + 1];
    float at[4][4], as_[4][4], ad[4];
#pragma unroll
    for (int i = 0; i < 4; i++) {
        ad[i] = 0.0f;
#pragma unroll
        for (int d = 0; d < 4; d++) { at[i][d] = 0.0f; as_[i][d] = 0.0f; }
    }

    for (int pos = rs; pos < re; pos++) {
        int src = g_ssrc[pos];
        uint2 eaw = *reinterpret_cast<const uint2*>(g_seah + (size_t)pos * 8 + j * 2);
        float2 ea0 = h2f(eaw.x), ea1 = h2f(eaw.y);
        const uint2* kb = reinterpret_cast<const uint2*>(g_kh + (size_t)src * 32 + j * 2);
        const uint2* vb = reinterpret_cast<const uint2*>(g_vh + (size_t)src * 32 + j * 2);

        float part[4];
#pragma unroll
        for (int i = 0; i < 4; i++) {
            uint2 kr = kb[i * 4];
            float2 q0 = h2f(qv[i].x), q1 = h2f(qv[i].y);
            float2 k0 = h2f(kr.x),  k1 = h2f(kr.y);
            float2 p0 = h2f(pv[i].x), p1 = h2f(pv[i].y);
            part[i] = q0.x * k0.x + q0.y * k0.y + q1.x * k1.x + q1.y * k1.y
                    + p0.x * ea0.x + p0.y * ea0.y + p1.x * ea1.x + p1.y * ea1.y;
        }
        part[j] += rj;   // after intra-quad sum, head h receives r_h exactly once
#pragma unroll
        for (int off = 1; off < 4; off <<= 1) {
#pragma unroll
            for (int i = 0; i < 4; i++) part[i] += __shfl_xor_sync(gmask, part[i], off);
        }
        float ex[4];
#pragma unroll
        for (int i = 0; i < 4; i++) ex[i] = __expf(part[i] * 0.25f);

#pragma unroll
        for (int i = 0; i < 4; i++) {
            ad[i] += ex[i];
            uint2 vr = vb[i * 4];
            float2 v0 = h2f(vr.x), v1 = h2f(vr.y);
            at[i][0] += ex[i] * v0.x; at[i][1] += ex[i] * v0.y;
            at[i][2] += ex[i] * v1.x; at[i][3] += ex[i] * v1.y;
            as_[i][0] += ex[i] * ea0.x; as_[i][1] += ex[i] * ea0.y;
            as_[i][2] += ex[i] * ea1.x; as_[i][3] += ex[i] * ea1.y;
        }
    }

    float* tb = g_t + (size_t)node * 64 + j * 4;
    float* sb = g_s + (size_t)node * 64 + j * 4;
#pragma unroll
    for (int i = 0; i < 4; i++) {
        float4 o;
        o.x = at[i][0]; o.y = at[i][1]; o.z = at[i][2]; o.w = at[i][3];
        *reinterpret_cast<float4*>(tb + i * 16) = o;
        o.x = as_[i][0]; o.y = as_[i][1]; o.z = as_[i][2]; o.w = as_[i][3];
        *reinterpret_cast<float4*>(sb + i * 16) = o;
    }
    if (j == 0) {
        float4 o; o.x = ad[0]; o.y = ad[1]; o.z = ad[2]; o.w = ad[3];
        *reinterpret_cast<float4*>(g_denom + (size_t)node * 4) = o;
    }
}

// ---------------- finalize: t = (t + We_h^T s + denom*be_h)/(denom+1e-16) + skip ----------------
__global__ void finalize_attn_kernel(const float* __restrict__ We, const float* __restrict__ be, int n) {
    __shared__ float sWe[16 * 64];
    __shared__ float sbe[64];
    const int tid = threadIdx.x;
    for (int i = tid; i < 1024; i += 256) sWe[i] = We[i];
    if (tid < 64) sbe[tid] = be[tid];
    __syncthreads();

    int idx = blockIdx.x * 256 + tid;
    if (idx >= n * 4) return;
    int node = idx >> 2, h = idx & 3;
    float den = g_denom[idx];
    float inv = 1.0f / (den + 1e-16f);

    const float4* sv = reinterpret_cast<const float4*>(g_s + (size_t)node * 64 + h * 16);
    float sarr[16];
#pragma unroll
    for (int j = 0; j < 4; j++) {
        float4 s4 = sv[j];
        sarr[4 * j] = s4.x; sarr[4 * j + 1] = s4.y; sarr[4 * j + 2] = s4.z; sarr[4 * j + 3] = s4.w;
    }
    float4 w[4];
#pragma unroll
    for (int j = 0; j < 4; j++) { w[j].x = 0.f; w[j].y = 0.f; w[j].z = 0.f; w[j].w = 0.f; }
#pragma unroll
    for (int c = 0; c < 16; c++) {
        float sc = sarr[c];
        const float4* wr = reinterpret_cast<const float4*>(&sWe[c * 64 + h * 16]);
#pragma unroll
        for (int j = 0; j < 4; j++) {
            float4 ww = wr[j];
            w[j].x += sc * ww.x; w[j].y += sc * ww.y;
            w[j].z += sc * ww.z; w[j].w += sc * ww.w;
        }
    }
    float4* tp = reinterpret_cast<float4*>(g_t + (size_t)node * 64 + h * 16);
    const float4* sp = reinterpret_cast<const float4*>(g_skip + (size_t)node * 64 + h * 16);
#pragma unroll
    for (int j = 0; j < 4; j++) {
        float4 t = tp[j], sk = sp[j];
        float bx = sbe[h * 16 + 4 * j + 0], by = sbe[h * 16 + 4 * j + 1];
        float bz = sbe[h * 16 + 4 * j + 2], bw = sbe[h * 16 + 4 * j + 3];
        t.x = (t.x + w[j].x + den * bx) * inv + sk.x;
        t.y = (t.y + w[j].y + den * by) * inv + sk.y;
        t.z = (t.z + w[j].z + den * bz) * inv + sk.z;
        t.w = (t.w + w[j].w + den * bw) * inv + sk.w;
        tp[j] = t;
    }
}

// ---------------- BN stats ----------------
__global__ void bn_stats_kernel(int n) {
    int tid = threadIdx.x;
    int c = tid & 63;
    int rowg = tid >> 6;
    float s = 0.0f, q = 0.0f;
    for (int r = blockIdx.x * 4 + rowg; r < n; r += gridDim.x * 4) {
        float v = g_t[(size_t)r * 64 + c];
        s += v; q += v * v;
    }
    __shared__ float ss[256], sq[256];
    ss[tid] = s; sq[tid] = q;
    __syncthreads();
    if (tid < 128) { ss[tid] += ss[tid + 128]; sq[tid] += sq[tid + 128]; }
    __syncthreads();
    if (tid < 64) {
        atomicAdd(&g_bnsum[tid], ss[tid] + ss[tid + 64]);
        atomicAdd(&g_bnsq[tid], sq[tid] + sq[tid + 64]);
    }
}

// ---------------- BN apply + GELU + residual ----------------
__global__ void bn_apply_kernel(const float* __restrict__ gamma, const float* __restrict__ beta, int n) {
    int idx = blockIdx.x * blockDim.x + threadIdx.x;
    if (idx >= n * 16) return;
    int c0 = (idx & 15) * 4;
    float invN = 1.0f / (float)n;
    float4 tv = reinterpret_cast<const float4*>(g_t)[idx];
    float4 hv = reinterpret_cast<const float4*>(g_h)[idx];
    float tt[4] = {tv.x, tv.y, tv.z, tv.w};
    float hh[4] = {hv.x, hv.y, hv.z, hv.w};
    float r[4];
#pragma unroll
    for (int k = 0; k < 4; k++) {
        int c = c0 + k;
        float mu = g_bnsum[c] * invN;
        float var = g_bnsq[c] * invN - mu * mu;
        float y = gamma[c] * (tt[k] - mu) * rsqrtf(var + 1e-5f) + beta[c];
        float gl = 0.5f * y * (1.0f + erff(y * 0.70710678118654752f));
        r[k] = gl + hh[k];
    }
    float4 o; o.x = r[0]; o.y = r[1]; o.z = r[2]; o.w = r[3];
    reinterpret_cast<float4*>(g_h)[idx] = o;
}

// ---------------- pooling ----------------
__global__ void clear_pool_kernel(int G) {
    int i = blockIdx.x * blockDim.x + threadIdx.x;
    if (i < G * 64) g_pool[i] = 0.0f;
    if (i < G) g_cnt[i] = 0.0f;
}

__global__ void pool_kernel(const int* __restrict__ batch, int n) {
    int idx = blockIdx.x * blockDim.x + threadIdx.x;
    if (idx >= n * 16) return;
    int node = idx >> 4, c4 = idx & 15;
    int g = batch[node];
    float4 v = reinterpret_cast<const float4*>(g_h)[idx];
    redAddV4(&g_pool[g * 64 + c4 * 4], v.x, v.y, v.z, v.w);
    if (c4 == 0) atomicAdd(&g_cnt[g], 1.0f);
}

// ---------------- regressor ----------------
__global__ void reg_kernel(const float* __restrict__ rw1, const float* __restrict__ rb1,
                           const float* __restrict__ rw2, const float* __restrict__ rb2,
                           float* __restrict__ out) {
    int g = blockIdx.x;
    int tid = threadIdx.x;  // 128 threads
    __shared__ float feat[128];
    __shared__ float hred[64];
    float invc = 1.0f / fmaxf(g_cnt[g], 1.0f);
    float s = g_pool[g * 64 + (tid & 63)];
    feat[tid] = (tid < 64) ? s * invc : s;
    __syncthreads();
    if (tid < 64) {
        float acc = rb1[tid];
#pragma unroll 8
        for (int i = 0; i < 128; i++) acc += feat[i] * rw1[i * 64 + tid];
        acc = fmaxf(acc, 0.0f);
        hred[tid] = acc * rw2[tid];
    }
    __syncthreads();
    if (tid < 32) {
        float v = hred[tid] + hred[tid + 32];
#pragma unroll
        for (int off = 16; off > 0; off >>= 1) v += __shfl_down_sync(0xffffffffu, v, off);
        if (tid == 0) out[g] = v + rb2[0];
    }
}

// ---------------- host orchestration ----------------
extern "C" void kernel_launch(void* const* d_in, const int* in_sizes, int n_in,
                              void* d_out, int out_size) {
    const float* x      = (const float*)d_in[0];
    const int*   ei     = (const int*)d_in[1];
    const float* eattr  = (const float*)d_in[2];
    const int*   batch  = (const int*)d_in[3];
    const float* node_w = (const float*)d_in[4];
    const float* node_b = (const float*)d_in[5];
    const float* Wq = (const float*)d_in[6];
    const float* bq = (const float*)d_in[7];
    const float* Wk = (const float*)d_in[8];
    const float* bk = (const float*)d_in[9];
    const float* Wv = (const float*)d_in[10];
    const float* bv = (const float*)d_in[11];
    const float* We = (const float*)d_in[12];
    const float* be = (const float*)d_in[13];
    const float* Ws = (const float*)d_in[14];
    const float* bs = (const float*)d_in[15];
    const float* gamma = (const float*)d_in[16];
    const float* beta  = (const float*)d_in[17];
    const float* rw1 = (const float*)d_in[18];
    const float* rb1 = (const float*)d_in[19];
    const float* rw2 = (const float*)d_in[20];
    const float* rb2 = (const float*)d_in[21];
    float* out = (float*)d_out;

    int n = in_sizes[0] / 32;   // nodes
    int e = in_sizes[2] / 16;   // edges
    int G = out_size;           // graphs
    int nb = divup(n, 1024);

    float* ph;
    cudaGetSymbolAddress((void**)&ph, g_h);

    lin32_kernel<<<divup(n, 128), 128>>>(x, node_w, node_b, ph, n);

    // Build dst-sorted edge stream + CSR rows (once; reused by all 3 layers)
    hist_clear_kernel<<<divup(n, 256), 256>>>(n);
    hist_kernel<<<divup(e, 256), 256>>>(ei, e);
    scan1_kernel<<<nb, 1024>>>(n);
    scan2_kernel<<<1, 32>>>(nb);
    scan3_kernel<<<nb, 1024>>>(n);
    scatter_kernel<<<divup(e, 256), 256>>>(ei, eattr, e);

    for (int l = 0; l < 3; l++) {
        const float* wq = Wq + (size_t)l * 64 * 64;
        const float* wk = Wk + (size_t)l * 64 * 64;
        const float* wv = Wv + (size_t)l * 64 * 64;
        const float* ws = Ws + (size_t)l * 64 * 64;
        const float* we = We + (size_t)l * 16 * 64;

        qkvs_kernel<<<divup(n, 64), 256>>>(ph, wq, bq + l * 64, wk, bk + l * 64,
                                           wv, bv + l * 64, ws, bs + l * 64,
                                           we, be + l * 64, n);
        edge_agg_kernel<<<divup((long long)n * 4, 256), 256>>>(n);
        finalize_attn_kernel<<<divup((long long)n * 4, 256), 256>>>(we, be + l * 64, n);
        bn_stats_kernel<<<2048, 256>>>(n);
        bn_apply_kernel<<<divup((long long)n * 16, 256), 256>>>(gamma + l * 64, beta + l * 64, n);
    }

    clear_pool_kernel<<<divup((long long)G * 64, 256), 256>>>(G);
    pool_kernel<<<divup((long long)n * 16, 256), 256>>>(batch, n);
    reg_kernel<<<G, 128>>>(rw1, rb1, rw2, rb2, out);
}

// round 12
// speedup vs baseline: 1.8899x; 1.2280x over previous
#include <cuda_runtime.h>
#include <cuda_fp16.h>
#include <math.h>
#include <stdint.h>

#define NMAX 100000
#define EMAX 1000000
#define GMAXG 512

// ---------------- scratch (device globals; no allocation allowed) ----------------
__device__ float   g_h[NMAX * 64];        // residual stream
__device__ float   g_t[NMAX * 64];        // post-attention / pre-BN buffer
__device__ __half2 g_qh[NMAX * 32];       // q fp16
__device__ __half2 g_kh[NMAX * 32];       // k fp16
__device__ __half2 g_vh[NMAX * 32];       // v fp16
__device__ __half2 g_ph[NMAX * 32];       // p_h = We_h @ q_h fp16
__device__ float   g_r[NMAX * 4];         // r_h = q_h . be_h
__device__ float   g_skip[NMAX * 64];
__device__ float   g_bnsum[64];
__device__ float   g_bnsq[64];
__device__ float   g_pool[GMAXG * 64];
__device__ float   g_cnt[GMAXG];
// CSR / sorted edge stream (built once per launch; edge list is layer-invariant)
__device__ int     g_cnt_n[NMAX];
__device__ int     g_row[NMAX + 1];
__device__ int     g_wp[NMAX];
__device__ int     g_bsum[128];
__device__ int     g_ssrc[EMAX];
__device__ __half2 g_seah[EMAX * 8];

static inline unsigned divup(long long a, int b) { return (unsigned)((a + b - 1) / b); }

__device__ __forceinline__ void redAddV4(float* addr, float a, float b, float c, float d) {
    asm volatile("red.global.add.v4.f32 [%0], {%1,%2,%3,%4};"
                 :: "l"(addr), "f"(a), "f"(b), "f"(c), "f"(d) : "memory");
}
__device__ __forceinline__ float2 h2f(unsigned u) {
    return __half22float2(*reinterpret_cast<const __half2*>(&u));
}
__device__ __forceinline__ unsigned f2tf32(float x) {
    unsigned r;
    asm("cvt.rna.tf32.f32 %0, %1;" : "=r"(r) : "f"(x));
    return r;
}
__device__ __forceinline__ void mma_tf32(float* d, const unsigned* a, unsigned b0, unsigned b1) {
    asm volatile(
        "mma.sync.aligned.m16n8k8.row.col.f32.tf32.tf32.f32 "
        "{%0,%1,%2,%3}, {%4,%5,%6,%7}, {%8,%9}, {%0,%1,%2,%3};"
        : "+f"(d[0]), "+f"(d[1]), "+f"(d[2]), "+f"(d[3])
        : "r"(a[0]), "r"(a[1]), "r"(a[2]), "r"(a[3]), "r"(b0), "r"(b1));
}

// ---------------- initial node linear: out[n,64] = in[n,32] @ W[32,64] + b ----------------
__global__ void lin32_kernel(const float* __restrict__ in, const float* __restrict__ W,
                             const float* __restrict__ bias, float* __restrict__ out, int n) {
    __shared__ float sW[32 * 64];
    __shared__ float sb[64];
    for (int i = threadIdx.x; i < 32 * 64; i += blockDim.x) sW[i] = W[i];
    if (threadIdx.x < 64) sb[threadIdx.x] = bias[threadIdx.x];
    __syncthreads();
    int node = blockIdx.x * blockDim.x + threadIdx.x;
    if (node >= n) return;
    float4 acc[16];
#pragma unroll
    for (int j = 0; j < 16; j++) {
        acc[j].x = sb[4 * j + 0]; acc[j].y = sb[4 * j + 1];
        acc[j].z = sb[4 * j + 2]; acc[j].w = sb[4 * j + 3];
    }
    const float4* inp = reinterpret_cast<const float4*>(in + (size_t)node * 32);
#pragma unroll
    for (int c = 0; c < 8; c++) {
        float4 x4 = inp[c];
        float xs[4] = {x4.x, x4.y, x4.z, x4.w};
#pragma unroll
        for (int kk = 0; kk < 4; kk++) {
            float x = xs[kk];
            const float4* wr = reinterpret_cast<const float4*>(&sW[(c * 4 + kk) * 64]);
#pragma unroll
            for (int j = 0; j < 16; j++) {
                float4 w = wr[j];
                acc[j].x += x * w.x; acc[j].y += x * w.y;
                acc[j].z += x * w.z; acc[j].w += x * w.w;
            }
        }
    }
    float4* op = reinterpret_cast<float4*>(out + (size_t)node * 64);
#pragma unroll
    for (int j = 0; j < 16; j++) op[j] = acc[j];
}

// ---------------- CSR build (once per launch) ----------------
__global__ void hist_clear_kernel(int n) {
    int i = blockIdx.x * blockDim.x + threadIdx.x;
    if (i < n) g_cnt_n[i] = 0;
}
__global__ void hist_kernel(const int* __restrict__ ei, int e) {
    int i = blockIdx.x * blockDim.x + threadIdx.x;
    if (i < e) atomicAdd(&g_cnt_n[ei[e + i]], 1);
}
__global__ void scan1_kernel(int n) {
    __shared__ int sm[1024];
    int i = blockIdx.x * 1024 + threadIdx.x;
    int v = (i < n) ? g_cnt_n[i] : 0;
    sm[threadIdx.x] = v;
    __syncthreads();
    for (int off = 1; off < 1024; off <<= 1) {
        int t = (threadIdx.x >= off) ? sm[threadIdx.x - off] : 0;
        __syncthreads();
        sm[threadIdx.x] += t;
        __syncthreads();
    }
    if (i < n) g_row[i + 1] = sm[threadIdx.x];
    if (threadIdx.x == 1023) g_bsum[blockIdx.x] = sm[1023];
}
__global__ void scan2_kernel(int nb) {
    if (threadIdx.x == 0) {
        int acc = 0;
        for (int b = 0; b < nb; b++) { int t = g_bsum[b]; g_bsum[b] = acc; acc += t; }
    }
}
__global__ void scan3_kernel(int n) {
    int i = blockIdx.x * 1024 + threadIdx.x;
    if (i < n) {
        int incl = g_row[i + 1] + g_bsum[blockIdx.x];
        g_row[i + 1] = incl;
        g_wp[i] = incl - g_cnt_n[i];
    }
    if (i == 0) g_row[0] = 0;
}
__global__ void scatter_kernel(const int* __restrict__ ei, const float* __restrict__ eattr, int e) {
    int eid = blockIdx.x * 256 + threadIdx.x;
    if (eid >= e) return;
    int dst = ei[e + eid];
    int pos = atomicAdd(&g_wp[dst], 1);
    g_ssrc[pos] = ei[eid];
    const float4* ea = reinterpret_cast<const float4*>(eattr + (size_t)eid * 16);
    __half2 hp[8];
#pragma unroll
    for (int jj = 0; jj < 4; jj++) {
        float4 v = ea[jj];
        hp[2 * jj]     = __floats2half2_rn(v.x, v.y);
        hp[2 * jj + 1] = __floats2half2_rn(v.z, v.w);
    }
    uint4* dp = reinterpret_cast<uint4*>(g_seah + (size_t)pos * 8);
    dp[0] = *reinterpret_cast<uint4*>(&hp[0]);
    dp[1] = *reinterpret_cast<uint4*>(&hp[4]);
}

// ---------------- fused q/k/v/skip (all tf32 mma) + p/r precompute ----------------
// block = 256 threads (8 warps) = 64 nodes. mma: warp w -> node group (w>>1)*16, col half (w&1)*32.
#define XS_STRIDE 68
#define SW_STRIDE 72
__global__ void qkvs_kernel(const float* __restrict__ h,
                            const float* __restrict__ Wq, const float* __restrict__ bq,
                            const float* __restrict__ Wk, const float* __restrict__ bk,
                            const float* __restrict__ Wv, const float* __restrict__ bv,
                            const float* __restrict__ Ws, const float* __restrict__ bs,
                            const float* __restrict__ We, const float* __restrict__ be,
                            int n) {
    __shared__ float xs[64 * XS_STRIDE];
    __shared__ float sW[64 * SW_STRIDE];
    __shared__ float sb[64];
    __shared__ float sWe[16 * 64];
    __shared__ float sbe[64];
    __shared__ __half qbuf[64 * 64];
    const int tid = threadIdx.x;
    const int base = blockIdx.x * 64;

    if (blockIdx.x == 0 && tid < 64) { g_bnsum[tid] = 0.0f; g_bnsq[tid] = 0.0f; }

    for (int idx = tid; idx < 64 * 16; idx += 256) {
        int nl = idx >> 4, kk = idx & 15;
        int gn = base + nl;
        if (gn < n) {
            float4 x4 = reinterpret_cast<const float4*>(h + (size_t)gn * 64)[kk];
            float* p = &xs[nl * XS_STRIDE + kk * 4];
            p[0] = x4.x; p[1] = x4.y; p[2] = x4.z; p[3] = x4.w;
        }
    }
    for (int i = tid; i < 1024; i += 256) sWe[i] = We[i];
    if (tid < 64) sbe[tid] = be[tid];

    const float* Wm[4] = {Wq, Wk, Wv, Ws};
    const float* bm[4] = {bq, bk, bv, bs};

    const int warp = tid >> 5, lane = tid & 31;
    const int g4 = warp >> 1;
    const int chalf = warp & 1;
    const int grp = lane >> 2;
    const int qd = lane & 3;
    const int nl = tid & 63;
    const int quart = tid >> 6;
    const int gn = base + nl;

    for (int m = 0; m < 4; m++) {
        __syncthreads();
        {
            const float* wsrc = Wm[m];
            for (int i = tid; i < 4096; i += 256) {
                sW[(i >> 6) * SW_STRIDE + (i & 63)] = __uint_as_float(f2tf32(wsrc[i]));
            }
            if (tid < 64) sb[tid] = bm[m][tid];
        }
        __syncthreads();

        float acc[4][4];
#pragma unroll
        for (int t = 0; t < 4; t++)
#pragma unroll
            for (int d = 0; d < 4; d++) acc[t][d] = 0.0f;

#pragma unroll
        for (int ks = 0; ks < 8; ks++) {
            unsigned a[4];
            const float* xr = &xs[(g4 * 16 + grp) * XS_STRIDE + ks * 8 + qd];
            a[0] = f2tf32(xr[0]);
            a[2] = f2tf32(xr[4]);
            a[1] = f2tf32(xr[8 * XS_STRIDE]);
            a[3] = f2tf32(xr[8 * XS_STRIDE + 4]);
#pragma unroll
            for (int t = 0; t < 4; t++) {
                int cb = chalf * 32 + t * 8;
                unsigned b0 = __float_as_uint(sW[(ks * 8 + qd) * SW_STRIDE + cb + grp]);
                unsigned b1 = __float_as_uint(sW[(ks * 8 + qd + 4) * SW_STRIDE + cb + grp]);
                mma_tf32(acc[t], a, b0, b1);
            }
        }

        int r0 = g4 * 16 + grp;
        if (m == 3) {
            // skip path: write fp32 directly
#pragma unroll
            for (int t = 0; t < 4; t++) {
                int col = chalf * 32 + t * 8 + qd * 2;
                if (base + r0 < n) {
                    float2 o; o.x = acc[t][0] + sb[col]; o.y = acc[t][1] + sb[col + 1];
                    *reinterpret_cast<float2*>(g_skip + (size_t)(base + r0) * 64 + col) = o;
                }
                if (base + r0 + 8 < n) {
                    float2 o; o.x = acc[t][2] + sb[col]; o.y = acc[t][3] + sb[col + 1];
                    *reinterpret_cast<float2*>(g_skip + (size_t)(base + r0 + 8) * 64 + col) = o;
                }
            }
        } else {
#pragma unroll
            for (int t = 0; t < 4; t++) {
                int col = chalf * 32 + t * 8 + qd * 2;
                __half2 hlo = __floats2half2_rn(acc[t][0] + sb[col], acc[t][1] + sb[col + 1]);
                __half2 hhi = __floats2half2_rn(acc[t][2] + sb[col], acc[t][3] + sb[col + 1]);
                if (m == 0) {
                    *reinterpret_cast<__half2*>(&qbuf[r0 * 64 + col]) = hlo;
                    *reinterpret_cast<__half2*>(&qbuf[(r0 + 8) * 64 + col]) = hhi;
                } else {
                    __half2* dst = (m == 1) ? g_kh : g_vh;
                    if (base + r0 < n)     dst[(size_t)(base + r0) * 32 + (col >> 1)] = hlo;
                    if (base + r0 + 8 < n) dst[(size_t)(base + r0 + 8) * 32 + (col >> 1)] = hhi;
                }
            }
            if (m == 0) {
                __syncthreads();
                if (gn < n) {
                    uint4 u0 = *reinterpret_cast<const uint4*>(&qbuf[nl * 64 + quart * 16]);
                    uint4 u1 = *reinterpret_cast<const uint4*>(&qbuf[nl * 64 + quart * 16 + 8]);
                    uint4* qp = reinterpret_cast<uint4*>(g_qh + (size_t)gn * 32 + quart * 8);
                    qp[0] = u0; qp[1] = u1;
                    float qv[16];
                    {
                        const unsigned* uw = reinterpret_cast<const unsigned*>(&u0);
#pragma unroll
                        for (int j = 0; j < 4; j++) {
                            float2 f = h2f(uw[j]); qv[2 * j] = f.x; qv[2 * j + 1] = f.y;
                        }
                        const unsigned* uw1 = reinterpret_cast<const unsigned*>(&u1);
#pragma unroll
                        for (int j = 0; j < 4; j++) {
                            float2 f = h2f(uw1[j]); qv[8 + 2 * j] = f.x; qv[9 + 2 * j] = f.y;
                        }
                    }
                    float pc[16];
#pragma unroll
                    for (int c = 0; c < 16; c++) {
                        const float4* wr = reinterpret_cast<const float4*>(&sWe[c * 64 + quart * 16]);
                        float s = 0.0f;
#pragma unroll
                        for (int j = 0; j < 4; j++) {
                            float4 w = wr[j];
                            s += w.x * qv[4 * j] + w.y * qv[4 * j + 1]
                               + w.z * qv[4 * j + 2] + w.w * qv[4 * j + 3];
                        }
                        pc[c] = s;
                    }
                    float rr = 0.0f;
#pragma unroll
                    for (int d = 0; d < 16; d++) rr += sbe[quart * 16 + d] * qv[d];
                    __half2 hp[8];
#pragma unroll
                    for (int j = 0; j < 8; j++) hp[j] = __floats2half2_rn(pc[2 * j], pc[2 * j + 1]);
                    uint4* pp = reinterpret_cast<uint4*>(g_ph + (size_t)gn * 32 + quart * 8);
                    pp[0] = *reinterpret_cast<uint4*>(&hp[0]);
                    pp[1] = *reinterpret_cast<uint4*>(&hp[4]);
                    g_r[gn * 4 + quart] = rr;
                }
            }
        }
    }
}

// ---------------- edge aggregation + finalize, fused; zero atomics ----------------
// 4 lanes per node walk its CSR range; epilogue applies We^T s + bias + normalize + skip.
__global__ void edge_agg_kernel(const float* __restrict__ We, const float* __restrict__ be, int n) {
    __shared__ float sWe[16 * 64];
    __shared__ float sbe[64];
    const int tid = threadIdx.x;
    for (int i = tid; i < 1024; i += 256) sWe[i] = We[i];
    if (tid < 64) sbe[tid] = be[tid];
    __syncthreads();

    int idx = blockIdx.x * 256 + tid;   // (node, j)
    if (idx >= n * 4) return;
    const int node = idx >> 2, j = idx & 3;
    const unsigned lane = tid & 31;
    const unsigned gmask = 0xFu << (lane & 28);
    const int lbase = lane & 28;

    // dst-side operands, loaded once per node
    const uint2* qb = reinterpret_cast<const uint2*>(g_qh + (size_t)node * 32 + j * 2);
    const uint2* pb = reinterpret_cast<const uint2*>(g_ph + (size_t)node * 32 + j * 2);
    uint2 qv[4], pv[4];
#pragma unroll
    for (int i = 0; i < 4; i++) { qv[i] = qb[i * 4]; pv[i] = pb[i * 4]; }
    const float rj = g_r[node * 4 + j];

    const int rs = g_row[node], re = g_row[node + 1];
    float at[4][4], as_[4][4], ad[4];
#pragma unroll
    for (int i = 0; i < 4; i++) {
        ad[i] = 0.0f;
#pragma unroll
        for (int d = 0; d < 4; d++) { at[i][d] = 0.0f; as_[i][d] = 0.0f; }
    }

    for (int pos = rs; pos < re; pos++) {
        int src = g_ssrc[pos];
        uint2 eaw = *reinterpret_cast<const uint2*>(g_seah + (size_t)pos * 8 + j * 2);
        float2 ea0 = h2f(eaw.x), ea1 = h2f(eaw.y);
        const uint2* kb = reinterpret_cast<const uint2*>(g_kh + (size_t)src * 32 + j * 2);
        const uint2* vb = reinterpret_cast<const uint2*>(g_vh + (size_t)src * 32 + j * 2);

        float part[4];
#pragma unroll
        for (int i = 0; i < 4; i++) {
            uint2 kr = kb[i * 4];
            float2 q0 = h2f(qv[i].x), q1 = h2f(qv[i].y);
            float2 k0 = h2f(kr.x),  k1 = h2f(kr.y);
            float2 p0 = h2f(pv[i].x), p1 = h2f(pv[i].y);
            part[i] = q0.x * k0.x + q0.y * k0.y + q1.x * k1.x + q1.y * k1.y
                    + p0.x * ea0.x + p0.y * ea0.y + p1.x * ea1.x + p1.y * ea1.y;
        }
        part[j] += rj;
#pragma unroll
        for (int off = 1; off < 4; off <<= 1) {
#pragma unroll
            for (int i = 0; i < 4; i++) part[i] += __shfl_xor_sync(gmask, part[i], off);
        }
        float ex[4];
#pragma unroll
        for (int i = 0; i < 4; i++) ex[i] = __expf(part[i] * 0.25f);

#pragma unroll
        for (int i = 0; i < 4; i++) {
            ad[i] += ex[i];
            uint2 vr = vb[i * 4];
            float2 v0 = h2f(vr.x), v1 = h2f(vr.y);
            at[i][0] += ex[i] * v0.x; at[i][1] += ex[i] * v0.y;
            at[i][2] += ex[i] * v1.x; at[i][3] += ex[i] * v1.y;
            as_[i][0] += ex[i] * ea0.x; as_[i][1] += ex[i] * ea0.y;
            as_[i][2] += ex[i] * ea1.x; as_[i][3] += ex[i] * ea1.y;
        }
    }

    // fused finalize: w = We_h^T s_h (s gathered across the quad), normalize, + skip
#pragma unroll
    for (int i = 0; i < 4; i++) {
        float w0 = 0.f, w1 = 0.f, w2 = 0.f, w3 = 0.f;
#pragma unroll
        for (int srcl = 0; srcl < 4; srcl++) {
#pragma unroll
            for (int cc = 0; cc < 4; cc++) {
                float sc = __shfl_sync(gmask, as_[i][cc], lbase + srcl);
                float4 ww = *reinterpret_cast<const float4*>(
                    &sWe[(srcl * 4 + cc) * 64 + i * 16 + j * 4]);
                w0 += sc * ww.x; w1 += sc * ww.y; w2 += sc * ww.z; w3 += sc * ww.w;
            }
        }
        float den = ad[i];
        float inv = 1.0f / (den + 1e-16f);
        int ch = i * 16 + j * 4;
        float4 sk = *reinterpret_cast<const float4*>(g_skip + (size_t)node * 64 + ch);
        float4 o;
        o.x = (at[i][0] + w0 + den * sbe[ch + 0]) * inv + sk.x;
        o.y = (at[i][1] + w1 + den * sbe[ch + 1]) * inv + sk.y;
        o.z = (at[i][2] + w2 + den * sbe[ch + 2]) * inv + sk.z;
        o.w = (at[i][3] + w3 + den * sbe[ch + 3]) * inv + sk.w;
        *reinterpret_cast<float4*>(g_t + (size_t)node * 64 + ch) = o;
    }
}

// ---------------- BN stats ----------------
__global__ void bn_stats_kernel(int n) {
    int tid = threadIdx.x;
    int c = tid & 63;
    int rowg = tid >> 6;
    float s = 0.0f, q = 0.0f;
    for (int r = blockIdx.x * 4 + rowg; r < n; r += gridDim.x * 4) {
        float v = g_t[(size_t)r * 64 + c];
        s += v; q += v * v;
    }
    __shared__ float ss[256], sq[256];
    ss[tid] = s; sq[tid] = q;
    __syncthreads();
    if (tid < 128) { ss[tid] += ss[tid + 128]; sq[tid] += sq[tid + 128]; }
    __syncthreads();
    if (tid < 64) {
        atomicAdd(&g_bnsum[tid], ss[tid] + ss[tid + 64]);
        atomicAdd(&g_bnsq[tid], sq[tid] + sq[tid + 64]);
    }
}

// ---------------- BN apply + GELU + residual ----------------
__global__ void bn_apply_kernel(const float* __restrict__ gamma, const float* __restrict__ beta, int n) {
    int idx = blockIdx.x * blockDim.x + threadIdx.x;
    if (idx >= n * 16) return;
    int c0 = (idx & 15) * 4;
    float invN = 1.0f / (float)n;
    float4 tv = reinterpret_cast<const float4*>(g_t)[idx];
    float4 hv = reinterpret_cast<const float4*>(g_h)[idx];
    float tt[4] = {tv.x, tv.y, tv.z, tv.w};
    float hh[4] = {hv.x, hv.y, hv.z, hv.w};
    float r[4];
#pragma unroll
    for (int k = 0; k < 4; k++) {
        int c = c0 + k;
        float mu = g_bnsum[c] * invN;
        float var = g_bnsq[c] * invN - mu * mu;
        float y = gamma[c] * (tt[k] - mu) * rsqrtf(var + 1e-5f) + beta[c];
        float gl = 0.5f * y * (1.0f + erff(y * 0.70710678118654752f));
        r[k] = gl + hh[k];
    }
    float4 o; o.x = r[0]; o.y = r[1]; o.z = r[2]; o.w = r[3];
    reinterpret_cast<float4*>(g_h)[idx] = o;
}

// ---------------- pooling ----------------
__global__ void clear_pool_kernel(int G) {
    int i = blockIdx.x * blockDim.x + threadIdx.x;
    if (i < G * 64) g_pool[i] = 0.0f;
    if (i < G) g_cnt[i] = 0.0f;
}

__global__ void pool_kernel(const int* __restrict__ batch, int n) {
    int idx = blockIdx.x * blockDim.x + threadIdx.x;
    if (idx >= n * 16) return;
    int node = idx >> 4, c4 = idx & 15;
    int g = batch[node];
    float4 v = reinterpret_cast<const float4*>(g_h)[idx];
    redAddV4(&g_pool[g * 64 + c4 * 4], v.x, v.y, v.z, v.w);
    if (c4 == 0) atomicAdd(&g_cnt[g], 1.0f);
}

// ---------------- regressor ----------------
__global__ void reg_kernel(const float* __restrict__ rw1, const float* __restrict__ rb1,
                           const float* __restrict__ rw2, const float* __restrict__ rb2,
                           float* __restrict__ out) {
    int g = blockIdx.x;
    int tid = threadIdx.x;  // 128 threads
    __shared__ float feat[128];
    __shared__ float hred[64];
    float invc = 1.0f / fmaxf(g_cnt[g], 1.0f);
    float s = g_pool[g * 64 + (tid & 63)];
    feat[tid] = (tid < 64) ? s * invc : s;
    __syncthreads();
    if (tid < 64) {
        float acc = rb1[tid];
#pragma unroll 8
        for (int i = 0; i < 128; i++) acc += feat[i] * rw1[i * 64 + tid];
        acc = fmaxf(acc, 0.0f);
        hred[tid] = acc * rw2[tid];
    }
    __syncthreads();
    if (tid < 32) {
        float v = hred[tid] + hred[tid + 32];
#pragma unroll
        for (int off = 16; off > 0; off >>= 1) v += __shfl_down_sync(0xffffffffu, v, off);
        if (tid == 0) out[g] = v + rb2[0];
    }
}

// ---------------- host orchestration ----------------
extern "C" void kernel_launch(void* const* d_in, const int* in_sizes, int n_in,
                              void* d_out, int out_size) {
    const float* x      = (const float*)d_in[0];
    const int*   ei     = (const int*)d_in[1];
    const float* eattr  = (const float*)d_in[2];
    const int*   batch  = (const int*)d_in[3];
    const float* node_w = (const float*)d_in[4];
    const float* node_b = (const float*)d_in[5];
    const float* Wq = (const float*)d_in[6];
    const float* bq = (const float*)d_in[7];
    const float* Wk = (const float*)d_in[8];
    const float* bk = (const float*)d_in[9];
    const float* Wv = (const float*)d_in[10];
    const float* bv = (const float*)d_in[11];
    const float* We = (const float*)d_in[12];
    const float* be = (const float*)d_in[13];
    const float* Ws = (const float*)d_in[14];
    const float* bs = (const float*)d_in[15];
    const float* gamma = (const float*)d_in[16];
    const float* beta  = (const float*)d_in[17];
    const float* rw1 = (const float*)d_in[18];
    const float* rb1 = (const float*)d_in[19];
    const float* rw2 = (const float*)d_in[20];
    const float* rb2 = (const float*)d_in[21];
    float* out = (float*)d_out;

    int n = in_sizes[0] / 32;   // nodes
    int e = in_sizes[2] / 16;   // edges
    int G = out_size;           // graphs
    int nb = divup(n, 1024);

    float* ph;
    cudaGetSymbolAddress((void**)&ph, g_h);

    lin32_kernel<<<divup(n, 128), 128>>>(x, node_w, node_b, ph, n);

    // Build dst-sorted edge stream + CSR rows (once; reused by all 3 layers)
    hist_clear_kernel<<<divup(n, 256), 256>>>(n);
    hist_kernel<<<divup(e, 256), 256>>>(ei, e);
    scan1_kernel<<<nb, 1024>>>(n);
    scan2_kernel<<<1, 32>>>(nb);
    scan3_kernel<<<nb, 1024>>>(n);
    scatter_kernel<<<divup(e, 256), 256>>>(ei, eattr, e);

    for (int l = 0; l < 3; l++) {
        const float* wq = Wq + (size_t)l * 64 * 64;
        const float* wk = Wk + (size_t)l * 64 * 64;
        const float* wv = Wv + (size_t)l * 64 * 64;
        const float* ws = Ws + (size_t)l * 64 * 64;
        const float* we = We + (size_t)l * 16 * 64;

        qkvs_kernel<<<divup(n, 64), 256>>>(ph, wq, bq + l * 64, wk, bk + l * 64,
                                           wv, bv + l * 64, ws, bs + l * 64,
                                           we, be + l * 64, n);
        edge_agg_kernel<<<divup((long long)n * 4, 256), 256>>>(we, be + l * 64, n);
        bn_stats_kernel<<<2048, 256>>>(n);
        bn_apply_kernel<<<divup((long long)n * 16, 256), 256>>>(gamma + l * 64, beta + l * 64, n);
    }

    clear_pool_kernel<<<divup((long long)G * 64, 256), 256>>>(G);
    pool_kernel<<<divup((long long)n * 16, 256), 256>>>(batch, n);
    reg_kernel<<<G, 128>>>(rw1, rb1, rw2, rb2, out);
}